// round 10
// baseline (speedup 1.0000x reference)
#include <cuda_runtime.h>
#include <mma.h>
#include <cstdint>

using namespace nvcuda;

// ---------------------------------------------------------------------------
// Model_57183194578962 — fused neighbor-attention + cosine loss
// B=512, N=100, E=512, D_MODEL=1024, H=8, DEPTH=128, VOCAB=50000
//
// Round 9: wmma tf32 split GEMMs (K-extension: A'=[Ahi|Alo|Ahi],
// B'=[Bhi;Bhi;Blo]). Epilogue fixed: each lane writes TWO adjacent float4s
// (cols cc and cc+4) for row rr=lane>>1 — full 16x16 coverage, in-bounds.
// ---------------------------------------------------------------------------

#define Bsz 512
#define Nn  100
#define Ee  512
#define DM  1024
#define Hh  8
#define DEPTH 128

// ------------------------- static scratch ----------------------------------
__device__ float g_Xq[2 * Bsz * DM];
__device__ float g_Q [2 * Bsz * DM];
__device__ float g_U [16 * Bsz * Ee];        // u_top  [(bq)*8+h][512]
__device__ float g_r4[16 * Bsz * 4];
__device__ float g_c0[16 * Bsz];
__device__ float g_xbar[16 * Bsz * Ee];
__device__ float g_wpos[16 * Bsz * 4];
__device__ float g_att[2 * Bsz * DM];
__device__ float g_O [2 * Bsz * DM];
__device__ float g_enc[Bsz * Ee];
__device__ float g_Mv[4 * DM], g_cv[DM];
__device__ float g_Mc[4 * Ee], g_cc[Ee];
__device__ float g_Rk[4 * DM], g_s1[DM];

// ---------------------------------------------------------------------------
// WMMA tf32 split GEMM engine.
//   C[M,N] = A @ B (+bias), ~fp32 via 3-phase tf32 split over extended K.
//   CTA tile 64(M) x 128(N), k-chunk 16, double buffered. 256 threads,
//   8 warps as 2(M) x 4(N), each warp a 32x32 tile (4 wmma frags).
//   NT:  B[n][k] row-major source (for U = Q @ Wk_h^T).
//   POOL: A row m is max(Asrc[2m], Asrc[2m+1])  (pool fused into enc GEMM).
// ---------------------------------------------------------------------------
__device__ __forceinline__ float tf32_cvt(float x, bool lo) {
    float h = wmma::__float_to_tf32(x);
    return lo ? wmma::__float_to_tf32(x - h) : h;
}

#define ALD 20
#define BLD 136
#define BLDT 20

template<bool NT, bool POOL>
__global__ void __launch_bounds__(256) wmma_gemm(
        const float* __restrict__ A0, int lda, long az,
        const float* __restrict__ B0, int ldb, long bz,
        float* __restrict__ C0, int ldc, long cz,
        const float* __restrict__ bias, int K) {
    const float* A = A0 + (size_t)blockIdx.z * az;
    const float* B = B0 + (size_t)blockIdx.z * bz;
    float*       C = C0 + (size_t)blockIdx.z * cz;

    __shared__ float As[2][64 * ALD];          // [m][k] ld=ALD
    __shared__ float Bs[2][2560];              // NN: [k][n] ld=136 ; NT: [n][k] ld=20
    __shared__ float sbias[16 * 128];          // replicated bias rows
    __shared__ float stage[8 * 256];           // epilogue staging (per warp 16x16)

    int tid = threadIdx.x;
    int warp = tid >> 5, lane = tid & 31;
    int row0 = blockIdx.y * 64, col0 = blockIdx.x * 128;
    int wm = warp >> 2, wn = warp & 3;
    int m0 = wm * 32, n0 = wn * 32;

    // thread load mapping
    int arr = tid >> 2, ak4 = (tid & 3) << 2;           // A: 64 x 16
    int bk  = tid >> 4, bn8 = (tid & 15) << 3;          // B NN: 16 x 128
    int bi  = tid >> 1, bk8 = (tid & 1) << 3;           // B NT: 128 x 16

    // bias rows (replicated x16)
    for (int idx = tid; idx < 16 * 128; idx += 256)
        sbias[idx] = bias ? bias[col0 + (idx & 127)] : 0.f;

    const int KC16 = K >> 4;        // k-chunks per phase
    const int NC = 3 * KC16;

    float4 fa, fb0, fb1;
    auto fetch = [&](int c) {
        int p = c / KC16;
        int kb = (c - p * KC16) << 4;
        if (POOL) {
            float4 x = *(const float4*)(A + (size_t)(2 * (row0 + arr)) * lda + kb + ak4);
            float4 y = *(const float4*)(A + (size_t)(2 * (row0 + arr) + 1) * lda + kb + ak4);
            fa.x = fmaxf(x.x, y.x); fa.y = fmaxf(x.y, y.y);
            fa.z = fmaxf(x.z, y.z); fa.w = fmaxf(x.w, y.w);
        } else {
            fa = *(const float4*)(A + (size_t)(row0 + arr) * lda + kb + ak4);
        }
        if (NT) {
            fb0 = *(const float4*)(B + (size_t)(col0 + bi) * ldb + kb + bk8);
            fb1 = *(const float4*)(B + (size_t)(col0 + bi) * ldb + kb + bk8 + 4);
        } else {
            fb0 = *(const float4*)(B + (size_t)(kb + bk) * ldb + col0 + bn8);
            fb1 = *(const float4*)(B + (size_t)(kb + bk) * ldb + col0 + bn8 + 4);
        }
    };
    auto commit = [&](int c, int buf) {
        int p = c / KC16;
        bool aLo = (p == 1), bLo = (p == 2);
        float* ap = &As[buf][arr * ALD + ak4];
        ap[0] = tf32_cvt(fa.x, aLo); ap[1] = tf32_cvt(fa.y, aLo);
        ap[2] = tf32_cvt(fa.z, aLo); ap[3] = tf32_cvt(fa.w, aLo);
        if (NT) {
            float* bp = &Bs[buf][bi * BLDT + bk8];
            bp[0] = tf32_cvt(fb0.x, bLo); bp[1] = tf32_cvt(fb0.y, bLo);
            bp[2] = tf32_cvt(fb0.z, bLo); bp[3] = tf32_cvt(fb0.w, bLo);
            bp[4] = tf32_cvt(fb1.x, bLo); bp[5] = tf32_cvt(fb1.y, bLo);
            bp[6] = tf32_cvt(fb1.z, bLo); bp[7] = tf32_cvt(fb1.w, bLo);
        } else {
            float* bp = &Bs[buf][bk * BLD + bn8];
            bp[0] = tf32_cvt(fb0.x, bLo); bp[1] = tf32_cvt(fb0.y, bLo);
            bp[2] = tf32_cvt(fb0.z, bLo); bp[3] = tf32_cvt(fb0.w, bLo);
            bp[4] = tf32_cvt(fb1.x, bLo); bp[5] = tf32_cvt(fb1.y, bLo);
            bp[6] = tf32_cvt(fb1.z, bLo); bp[7] = tf32_cvt(fb1.w, bLo);
        }
    };

    // prologue
    fetch(0);
    commit(0, 0);
    __syncthreads();

    // accumulators (init with bias)
    wmma::fragment<wmma::accumulator, 16, 16, 8, float> acc[2][2];
    #pragma unroll
    for (int i = 0; i < 2; i++)
        #pragma unroll
        for (int j = 0; j < 2; j++)
            wmma::load_matrix_sync(acc[i][j], &sbias[n0 + 16 * j], 128,
                                   wmma::mem_row_major);

    for (int c = 0; c < NC; c++) {
        int buf = c & 1;
        if (c + 1 < NC) fetch(c + 1);
        #pragma unroll
        for (int k2 = 0; k2 < 2; k2++) {
            wmma::fragment<wmma::matrix_a, 16, 16, 8, wmma::precision::tf32,
                           wmma::row_major> a0, a1;
            wmma::load_matrix_sync(a0, &As[buf][(m0 +  0) * ALD + k2 * 8], ALD);
            wmma::load_matrix_sync(a1, &As[buf][(m0 + 16) * ALD + k2 * 8], ALD);
            if (NT) {
                wmma::fragment<wmma::matrix_b, 16, 16, 8, wmma::precision::tf32,
                               wmma::col_major> b0, b1;
                wmma::load_matrix_sync(b0, &Bs[buf][(n0 +  0) * BLDT + k2 * 8], BLDT);
                wmma::load_matrix_sync(b1, &Bs[buf][(n0 + 16) * BLDT + k2 * 8], BLDT);
                wmma::mma_sync(acc[0][0], a0, b0, acc[0][0]);
                wmma::mma_sync(acc[0][1], a0, b1, acc[0][1]);
                wmma::mma_sync(acc[1][0], a1, b0, acc[1][0]);
                wmma::mma_sync(acc[1][1], a1, b1, acc[1][1]);
            } else {
                wmma::fragment<wmma::matrix_b, 16, 16, 8, wmma::precision::tf32,
                               wmma::row_major> b0, b1;
                wmma::load_matrix_sync(b0, &Bs[buf][(k2 * 8) * BLD + n0], BLD);
                wmma::load_matrix_sync(b1, &Bs[buf][(k2 * 8) * BLD + n0 + 16], BLD);
                wmma::mma_sync(acc[0][0], a0, b0, acc[0][0]);
                wmma::mma_sync(acc[0][1], a0, b1, acc[0][1]);
                wmma::mma_sync(acc[1][0], a1, b0, acc[1][0]);
                wmma::mma_sync(acc[1][1], a1, b1, acc[1][1]);
            }
        }
        if (c + 1 < NC) commit(c + 1, buf ^ 1);
        __syncthreads();
    }

    // epilogue: stage each 16x16 frag in smem, then TWO float4s per lane:
    // row rr = lane>>1 (0..15), col chunks cc and cc+4 with cc = (lane&1)*8.
    // Covers 16 rows x 16 cols exactly. Max stage idx 15*16+15=255 (in-bounds).
    float* st = &stage[warp * 256];
    int rr = lane >> 1, cc = (lane & 1) << 3;
    #pragma unroll
    for (int i = 0; i < 2; i++)
        #pragma unroll
        for (int j = 0; j < 2; j++) {
            wmma::store_matrix_sync(st, acc[i][j], 16, wmma::mem_row_major);
            __syncwarp();
            int gr = row0 + m0 + 16 * i + rr;
            int gc = col0 + n0 + 16 * j + cc;
            float4 v0 = *(float4*)&st[rr * 16 + cc];
            *(float4*)(C + (size_t)gr * ldc + gc) = v0;
            float4 v1 = *(float4*)&st[rr * 16 + cc + 4];
            *(float4*)(C + (size_t)gr * ldc + gc + 4) = v1;
            __syncwarp();
        }
}

// ---------------------------------------------------------------------------
// Tiny fused matmuls: M_out[c][n] = sum_k W4[c][k]*Wbot[k][n],
//                     c_out[n]   = sum_k b_in[k]*Wbot[k][n] + b_out[n]
// ---------------------------------------------------------------------------
__global__ void fuse_small(const float* __restrict__ W4, const float* __restrict__ b_in,
                           const float* __restrict__ Wbot, const float* __restrict__ b_out,
                           float* __restrict__ M_out, float* __restrict__ c_out,
                           int K2, int Nout, int ldb) {
    int n = blockIdx.x * blockDim.x + threadIdx.x;
    if (n >= Nout) return;
    float m0 = 0.f, m1 = 0.f, m2 = 0.f, m3 = 0.f, c = 0.f;
    for (int k = 0; k < K2; k++) {
        float w = Wbot[(size_t)k * ldb + n];
        m0 += W4[k] * w;
        m1 += W4[K2 + k] * w;
        m2 += W4[2 * K2 + k] * w;
        m3 += W4[3 * K2 + k] * w;
        c  += b_in[k] * w;
    }
    M_out[n] = m0; M_out[Nout + n] = m1;
    M_out[2 * Nout + n] = m2; M_out[3 * Nout + n] = m3;
    c_out[n] = c + b_out[n];
}

// ---------------------------------------------------------------------------
__global__ void build_xq(const int* __restrict__ nt, const float* __restrict__ npos,
                         const float* __restrict__ text_table,
                         const float* __restrict__ pos_W, const float* __restrict__ pos_b,
                         float* __restrict__ Xq) {
    int r = blockIdx.x;               // 0..1023 = b*2 + i
    int b = r >> 1, i = r & 1;
    int id = nt[b * Nn + i];
    const float* trow = text_table + (size_t)id * Ee;
    const float* pp = npos + (size_t)(b * Nn + i) * 4;
    float p0 = pp[0], p1 = pp[1], p2 = pp[2], p3 = pp[3];
    float* xr = Xq + (size_t)r * DM;
    for (int j = threadIdx.x; j < Ee; j += blockDim.x) {
        xr[j] = trow[j];
        xr[Ee + j] = p0 * pos_W[j] + p1 * pos_W[Ee + j] + p2 * pos_W[2 * Ee + j]
                   + p3 * pos_W[3 * Ee + j] + pos_b[j];
    }
}

// ---------------------------------------------------------------------------
// Per-(bq,h) score constants via precomputed Rk/s1: one warp per (bq,h).
// ---------------------------------------------------------------------------
__global__ void __launch_bounds__(256) score_consts2(
        const float* __restrict__ Q, const float* __restrict__ Rk,
        const float* __restrict__ s1, float* __restrict__ r4, float* __restrict__ c0) {
    int warp = threadIdx.x >> 5, lane = threadIdx.x & 31;
    int i = blockIdx.x * 8 + warp;          // 0..8191
    int bq = i >> 3, h = i & 7;
    float4 qv = *(const float4*)(Q + (size_t)bq * DM + h * DEPTH + lane * 4);
    #pragma unroll
    for (int c = 0; c < 5; c++) {
        const float* src = (c < 4) ? (Rk + c * DM) : s1;
        float4 rv = *(const float4*)(src + h * DEPTH + lane * 4);
        float s = qv.x * rv.x + qv.y * rv.y + qv.z * rv.z + qv.w * rv.w;
        #pragma unroll
        for (int off = 16; off; off >>= 1) s += __shfl_xor_sync(0xffffffffu, s, off);
        if (lane == 0) {
            if (c < 4) r4[i * 4 + c] = s;
            else       c0[i] = s;
        }
    }
}

// ---------------------------------------------------------------------------
// Fused attention: scores (gather-dot) -> softmax -> xbar (gather-axpy).
// ---------------------------------------------------------------------------
#define ATTN_SMEM (13736 * 4)

__global__ void __launch_bounds__(256) attn_fused(
        const int* __restrict__ nt, const float* __restrict__ npos,
        const float* __restrict__ U, const float* __restrict__ r4,
        const float* __restrict__ c0, const float* __restrict__ text_table,
        float* __restrict__ xbar, float* __restrict__ wpos) {
    extern __shared__ float dyn[];
    float* sUt  = dyn;                  // [512][16] transposed u_top
    float* sT   = dyn + 8192;           // [100][33]
    float* sS   = dyn + 11492;          // [16][104]
    float* spos = dyn + 13156;          // [100][4]
    float* sr4  = dyn + 13556;          // [16][4]
    float* sc0  = dyn + 13620;          // [16]
    int*   sid  = (int*)(dyn + 13636);  // [100]

    int b = blockIdx.x, tid = threadIdx.x;
    int warp = tid >> 5, lane = tid & 31;

    for (int n = tid; n < Nn; n += 256) {
        int id = nt[b * Nn + n];
        sid[n] = id;
        float4 p = *(const float4*)(npos + (size_t)(b * Nn + n) * 4);
        spos[n * 4 + 0] = p.x; spos[n * 4 + 1] = p.y;
        spos[n * 4 + 2] = p.z; spos[n * 4 + 3] = p.w;
    }
    for (int idx = tid; idx < 16 * Ee; idx += 256) {
        int qh = idx >> 9, d = idx & 511;
        sUt[d * 16 + qh] = U[((size_t)b * 16 + qh) * Ee + d];
    }
    for (int idx = tid; idx < 64; idx += 256) sr4[idx] = r4[(size_t)b * 64 + idx];
    if (tid < 16) sc0[tid] = c0[(size_t)b * 16 + tid];
    __syncthreads();

    float m0 = (sid[0] == 0) ? 1.f : 0.f;
    float m1 = (sid[1] == 0) ? 1.f : 0.f;
    const float scale = 0.08838834764831845f;   // 1/sqrt(128)

    bool active = tid < 200;
    int qh0 = (tid & 7) * 2;
    int n0 = (tid >> 3) * 4;
    float acc[2][4] = {};

    for (int kc = 0; kc < 16; kc++) {
        for (int idx = tid; idx < Nn * 32; idx += 256) {
            int n = idx >> 5, d = idx & 31;
            sT[n * 33 + d] = text_table[(size_t)sid[n] * Ee + kc * 32 + d];
        }
        __syncthreads();
        if (active) {
            #pragma unroll
            for (int d = 0; d < 32; d++) {
                int gd = kc * 32 + d;
                float2 u2 = *(float2*)&sUt[gd * 16 + qh0];
                #pragma unroll
                for (int i = 0; i < 4; i++) {
                    float t = sT[(n0 + i) * 33 + d];
                    acc[0][i] += u2.x * t;
                    acc[1][i] += u2.y * t;
                }
            }
        }
        __syncthreads();
    }
    if (active) {
        #pragma unroll
        for (int j = 0; j < 2; j++) {
            int qh = qh0 + j;
            float mq = (qh < 8) ? m0 : m1;
            #pragma unroll
            for (int i = 0; i < 4; i++) {
                int n = n0 + i;
                float s = acc[j][i]
                        + spos[n * 4 + 0] * sr4[qh * 4 + 0]
                        + spos[n * 4 + 1] * sr4[qh * 4 + 1]
                        + spos[n * 4 + 2] * sr4[qh * 4 + 2]
                        + spos[n * 4 + 3] * sr4[qh * 4 + 3]
                        + sc0[qh];
                float mn = (sid[n] == 0) ? 1.f : 0.f;
                sS[qh * 104 + n] = s * scale + mq * mn * (-1e9f);
            }
        }
    }
    __syncthreads();

    for (int r = warp; r < 16; r += 8) {
        float* row = sS + r * 104;
        float mx = -1e30f;
        for (int jn = lane; jn < Nn; jn += 32) mx = fmaxf(mx, row[jn]);
        #pragma unroll
        for (int off = 16; off; off >>= 1)
            mx = fmaxf(mx, __shfl_xor_sync(0xffffffffu, mx, off));
        float ev[4]; int cnt = 0; float sum = 0.f;
        for (int jn = lane; jn < Nn; jn += 32) {
            float e = expf(row[jn] - mx);
            ev[cnt++] = e; sum += e;
        }
        #pragma unroll
        for (int off = 16; off; off >>= 1)
            sum += __shfl_xor_sync(0xffffffffu, sum, off);
        float inv = 1.f / sum;
        cnt = 0;
        for (int jn = lane; jn < Nn; jn += 32) row[jn] = ev[cnt++] * inv;
    }
    __syncthreads();

    if (tid < 64) {
        int qh = tid >> 2, c = tid & 3;
        float s = 0.f;
        for (int n = 0; n < Nn; n++) s += sS[qh * 104 + n] * spos[n * 4 + c];
        wpos[((size_t)b * 16 + qh) * 4 + c] = s;
    }

    float* sT2 = dyn;                   // reuse [16][512]
    int qh = tid & 15, dg = tid >> 4;
    float xa[32] = {};
    for (int nc = 0; nc < 7; nc++) {
        __syncthreads();
        for (int idx = tid; idx < 16 * Ee; idx += 256) {
            int rr = idx >> 9, d = idx & 511;
            int n = nc * 16 + rr;
            if (n < Nn) sT2[rr * Ee + d] = text_table[(size_t)sid[n] * Ee + d];
        }
        __syncthreads();
        int nmax = min(16, Nn - nc * 16);
        for (int rr = 0; rr < nmax; rr++) {
            float w = sS[qh * 104 + nc * 16 + rr];
            const float* tp = sT2 + rr * Ee + dg;
            #pragma unroll
            for (int j = 0; j < 32; j++) xa[j] += w * tp[16 * j];
        }
    }
    __syncthreads();
    float* sX = dyn;
    #pragma unroll
    for (int j = 0; j < 32; j++) sX[qh * Ee + dg + 16 * j] = xa[j];
    __syncthreads();
    for (int idx = tid; idx < 16 * Ee; idx += 256) {
        int q2 = idx >> 9, d = idx & 511;
        xbar[((size_t)b * 16 + q2) * Ee + d] = sX[idx];
    }
}

// ---------------------------------------------------------------------------
// att += wpos @ Mv + cv (elementwise epilogue, vectorized)
// ---------------------------------------------------------------------------
__global__ void att_post(float* __restrict__ att, const float* __restrict__ wpos,
                         const float* __restrict__ Mv, const float* __restrict__ cv) {
    int idx = blockIdx.x * blockDim.x + threadIdx.x;
    if (idx >= 2 * Bsz * DM / 4) return;
    int r = idx >> 8;
    int c4 = (idx & 255) * 4;
    int z = c4 >> 7;
    const float* wp = wpos + ((size_t)r * 8 + z) * 4;
    float w0 = wp[0], w1 = wp[1], w2 = wp[2], w3 = wp[3];
    float4 v = *(float4*)(att + (size_t)r * DM + c4);
    #pragma unroll
    for (int u = 0; u < 4; u++) {
        int c = c4 + u;
        (&v.x)[u] += cv[c] + w0 * Mv[c] + w1 * Mv[DM + c]
                   + w2 * Mv[2 * DM + c] + w3 * Mv[3 * DM + c];
    }
    *(float4*)(att + (size_t)r * DM + c4) = v;
}

// ---------------------------------------------------------------------------
__global__ void __launch_bounds__(128) cosine_kernel(
        const float* __restrict__ enc, const float* __restrict__ cand_pos,
        const float* __restrict__ Mc, const int* __restrict__ field_id,
        const float* __restrict__ field_table, float* __restrict__ out) {
    __shared__ float red[3][4];
    int b = blockIdx.x, t = threadIdx.x;
    int warp = t >> 5, lane = t & 31;
    const float* fp = field_table + (size_t)field_id[b] * Ee;
    float4 cp = *(const float4*)(cand_pos + (size_t)b * 4);
    float na = 0.f, nb = 0.f, dp = 0.f;
    for (int j = t; j < Ee; j += 128) {
        float e = enc[(size_t)b * Ee + j]
                + cp.x * Mc[j] + cp.y * Mc[Ee + j]
                + cp.z * Mc[2 * Ee + j] + cp.w * Mc[3 * Ee + j];
        float f = fp[j];
        na += e * e; nb += f * f; dp += e * f;
    }
    #pragma unroll
    for (int off = 16; off; off >>= 1) {
        na += __shfl_xor_sync(0xffffffffu, na, off);
        nb += __shfl_xor_sync(0xffffffffu, nb, off);
        dp += __shfl_xor_sync(0xffffffffu, dp, off);
    }
    if (lane == 0) { red[0][warp] = na; red[1][warp] = nb; red[2][warp] = dp; }
    __syncthreads();
    if (t == 0) {
        na = red[0][0] + red[0][1] + red[0][2] + red[0][3];
        nb = red[1][0] + red[1][1] + red[1][2] + red[1][3];
        dp = red[2][0] + red[2][1] + red[2][2] + red[2][3];
        out[b] = -dp * rsqrtf(fmaxf(na, 1e-12f)) * rsqrtf(fmaxf(nb, 1e-12f));
    }
}

// ---------------------------------------------------------------------------
extern "C" void kernel_launch(void* const* d_in, const int* in_sizes, int n_in,
                              void* d_out, int out_size) {
    const int*   field_id   = (const int*)  d_in[0];
    const float* cand_pos   = (const float*)d_in[1];
    const int*   nt         = (const int*)  d_in[2];
    const float* npos       = (const float*)d_in[3];
    const float* text_table = (const float*)d_in[4];
    const float* field_tab  = (const float*)d_in[5];
    const float* cand_W     = (const float*)d_in[6];
    const float* cand_b     = (const float*)d_in[7];
    const float* pos_W      = (const float*)d_in[8];
    const float* pos_b      = (const float*)d_in[9];
    const float* Wq         = (const float*)d_in[10];
    const float* bq         = (const float*)d_in[11];
    const float* Wk         = (const float*)d_in[12];
    const float* bk         = (const float*)d_in[13];
    const float* Wv         = (const float*)d_in[14];
    const float* bv         = (const float*)d_in[15];
    const float* Wo         = (const float*)d_in[16];
    const float* bo         = (const float*)d_in[17];
    const float* proj_W     = (const float*)d_in[18];
    const float* proj_b     = (const float*)d_in[19];
    float* out = (float*)d_out;

    float *Xq, *Qb, *Ub, *r4b, *c0b, *xbarb, *wposb, *attb, *Ob, *encb;
    float *Mvp, *cvp, *Mcp, *ccp, *Rkp, *s1p;
    cudaGetSymbolAddress((void**)&Xq,    g_Xq);
    cudaGetSymbolAddress((void**)&Qb,    g_Q);
    cudaGetSymbolAddress((void**)&Ub,    g_U);
    cudaGetSymbolAddress((void**)&r4b,   g_r4);
    cudaGetSymbolAddress((void**)&c0b,   g_c0);
    cudaGetSymbolAddress((void**)&xbarb, g_xbar);
    cudaGetSymbolAddress((void**)&wposb, g_wpos);
    cudaGetSymbolAddress((void**)&attb,  g_att);
    cudaGetSymbolAddress((void**)&Ob,    g_O);
    cudaGetSymbolAddress((void**)&encb,  g_enc);
    cudaGetSymbolAddress((void**)&Mvp,   g_Mv);
    cudaGetSymbolAddress((void**)&cvp,   g_cv);
    cudaGetSymbolAddress((void**)&Mcp,   g_Mc);
    cudaGetSymbolAddress((void**)&ccp,   g_cc);
    cudaGetSymbolAddress((void**)&Rkp,   g_Rk);
    cudaGetSymbolAddress((void**)&s1p,   g_s1);

    cudaFuncSetAttribute(attn_fused,
                         cudaFuncAttributeMaxDynamicSharedMemorySize, ATTN_SMEM);

    // rank-4 folds
    fuse_small<<<4, 256>>>(pos_W, pos_b, Wv + (size_t)Ee * DM, bv, Mvp, cvp, Ee, DM, DM);
    fuse_small<<<2, 256>>>(cand_W, cand_b, proj_W, proj_b, Mcp, ccp, Ee, Ee, Ee);
    fuse_small<<<4, 256>>>(pos_W, pos_b, Wk + (size_t)Ee * DM, bk, Rkp, s1p, Ee, DM, DM);

    // query inputs (rows 0,1 only)
    build_xq<<<2 * Bsz, 256>>>(nt, npos, text_table, pos_W, pos_b, Xq);

    // Q = Xq @ Wq + bq  (1024 x 1024 x 1024)
    wmma_gemm<false, false><<<dim3(8, 16, 1), 256>>>(
        Xq, DM, 0, Wq, DM, 0, Qb, DM, 0, bq, DM);

    // U_top[(bq)*8+h][i<512] = q_h @ Wk_top_h^T  (8 x [1024 x 512 x 128] NT)
    wmma_gemm<true, false><<<dim3(4, 16, 8), 256>>>(
        Qb, DM, 128, Wk, DM, 128, Ub, 8 * Ee, Ee, nullptr, DEPTH);

    // per-(bq,h) score constants from Rk/s1
    score_consts2<<<16 * Bsz / 8, 256>>>(Qb, Rkp, s1p, r4b, c0b);

    // fused gather-scores -> softmax -> xbar/wpos
    attn_fused<<<Bsz, 256, ATTN_SMEM>>>(nt, npos, Ub, r4b, c0b, text_table,
                                        xbarb, wposb);

    // att = xbar @ Wv_top  (8 x [1024 x 128 x 512], batched via z)
    wmma_gemm<false, false><<<dim3(1, 16, 8), 256>>>(
        xbarb, 8 * Ee, Ee, Wv, DM, 128, attb, DM, 128, nullptr, Ee);
    // att += wpos @ Mv + cv
    att_post<<<(2 * Bsz * DM / 4 + 255) / 256, 256>>>(attb, wposb, Mvp, cvp);

    // O = att @ Wo + bo
    wmma_gemm<false, false><<<dim3(8, 16, 1), 256>>>(
        attb, DM, 0, Wo, DM, 0, Ob, DM, 0, bo, DM);

    // enc = max-pool(O rows 2b,2b+1) @ proj_W[512:,:] + cc   (pool fused)
    wmma_gemm<false, true><<<dim3(4, 8, 1), 256>>>(
        Ob, DM, 0, proj_W + (size_t)Ee * Ee, Ee, 0, encb, Ee, 0, ccp, DM);

    // cosine loss
    cosine_kernel<<<Bsz, 128>>>(encb, cand_pos, Mcp, field_id, field_tab, out);
}

// round 11
// speedup vs baseline: 1.2031x; 1.2031x over previous
#include <cuda_runtime.h>
#include <mma.h>
#include <cstdint>

using namespace nvcuda;

// ---------------------------------------------------------------------------
// Model_57183194578962 — fused neighbor-attention + cosine loss
// B=512, N=100, E=512, D_MODEL=1024, H=8, DEPTH=128, VOCAB=50000
//
// Round 10: tf32-split wmma engine v2 — hi/lo tiles BOTH resident in smem,
// 3 passes per loaded chunk (1x global traffic, 1/3 syncs of v1).
// Q GEMM halved algebraically (Q = t@Wq_top + rank4).
// ---------------------------------------------------------------------------

#define Bsz 512
#define Nn  100
#define Ee  512
#define DM  1024
#define Hh  8
#define DEPTH 128

// ------------------------- static scratch ----------------------------------
__device__ float g_Tq[2 * Bsz * Ee];         // gathered text rows for q   [1024,512]
__device__ float g_Q [2 * Bsz * DM];
__device__ float g_U [16 * Bsz * Ee];        // u_top  [(bq)*8+h][512]
__device__ float g_r4[16 * Bsz * 4];
__device__ float g_c0[16 * Bsz];
__device__ float g_xbar[16 * Bsz * Ee];
__device__ float g_wpos[16 * Bsz * 4];
__device__ float g_att[2 * Bsz * DM];
__device__ float g_O [2 * Bsz * DM];
__device__ float g_enc[Bsz * Ee];
__device__ float g_Mv[4 * DM], g_cv[DM];
__device__ float g_Mc[4 * Ee], g_cc[Ee];
__device__ float g_Rk[4 * DM], g_s1[DM];
__device__ float g_Rq[4 * DM], g_sq[DM];

// ---------------------------------------------------------------------------
// WMMA tf32 split GEMM engine v2.
//   C = A @ B (+bias).  CTA tile 64(M) x 128(N), k-chunk 16, double buffered.
//   Both hi and lo tf32 tiles resident per chunk; 3 mma passes per load:
//   hi*hi + hi*lo + lo*hi  (== fp32 to ~2^-22).
//   8 warps as 2(M) x 4(N), warp tile 32x32.
//   NT: B[n][k] row-major source.  POOL: A row m = max(Asrc[2m], Asrc[2m+1]).
// Dynamic smem (floats):
//   As:   [buf*2+hl]*1280   (64 x 20)            [0, 5120)
//   Bs:   5120 + [buf*2+hl]*2560                 [5120, 15360)
//   stage:15360 + warp*256                       [15360, 17408)
// ---------------------------------------------------------------------------
#define ALD 20
#define BLDNN 136
#define BLDNT 20
#define GSMEM_BYTES (17408 * 4)

__device__ __forceinline__ float tf32_hi(float x) { return wmma::__float_to_tf32(x); }

template<bool NT, bool POOL>
__global__ void __launch_bounds__(256) wmma_gemm2(
        const float* __restrict__ A0, int lda, long az,
        const float* __restrict__ B0, int ldb, long bz,
        float* __restrict__ C0, int ldc, long cz,
        const float* __restrict__ bias, int K) {
    const float* A = A0 + (size_t)blockIdx.z * az;
    const float* B = B0 + (size_t)blockIdx.z * bz;
    float*       C = C0 + (size_t)blockIdx.z * cz;

    extern __shared__ float dynsm[];
    float* Asm   = dynsm;
    float* Bsm   = dynsm + 5120;
    float* stage = dynsm + 15360;

    int tid = threadIdx.x;
    int warp = tid >> 5, lane = tid & 31;
    int row0 = blockIdx.y * 64, col0 = blockIdx.x * 128;
    int wm = warp >> 2, wn = warp & 3;
    int m0 = wm * 32, n0 = wn * 32;

    // thread load mapping
    int arr = tid >> 2, ak4 = (tid & 3) << 2;           // A: 64 x 16
    int bk  = tid >> 4, bn8 = (tid & 15) << 3;          // B NN: 16 x 128
    int bi  = tid >> 1, bk8 = (tid & 1) << 3;           // B NT: 128 x 16

    const int nk = K >> 4;

    float4 fa, fb0, fb1;
    auto fetch = [&](int c) {
        int kb = c << 4;
        if (POOL) {
            float4 x = *(const float4*)(A + (size_t)(2 * (row0 + arr)) * lda + kb + ak4);
            float4 y = *(const float4*)(A + (size_t)(2 * (row0 + arr) + 1) * lda + kb + ak4);
            fa.x = fmaxf(x.x, y.x); fa.y = fmaxf(x.y, y.y);
            fa.z = fmaxf(x.z, y.z); fa.w = fmaxf(x.w, y.w);
        } else {
            fa = *(const float4*)(A + (size_t)(row0 + arr) * lda + kb + ak4);
        }
        if (NT) {
            fb0 = *(const float4*)(B + (size_t)(col0 + bi) * ldb + kb + bk8);
            fb1 = *(const float4*)(B + (size_t)(col0 + bi) * ldb + kb + bk8 + 4);
        } else {
            fb0 = *(const float4*)(B + (size_t)(kb + bk) * ldb + col0 + bn8);
            fb1 = *(const float4*)(B + (size_t)(kb + bk) * ldb + col0 + bn8 + 4);
        }
    };
    auto commit = [&](int buf) {
        float* ah = &Asm[(buf * 2 + 0) * 1280 + arr * ALD + ak4];
        float* al = &Asm[(buf * 2 + 1) * 1280 + arr * ALD + ak4];
        #pragma unroll
        for (int u = 0; u < 4; u++) {
            float x = (&fa.x)[u];
            float h = tf32_hi(x);
            ah[u] = h; al[u] = tf32_hi(x - h);
        }
        float* bh;
        float* bl;
        if (NT) {
            bh = &Bsm[(buf * 2 + 0) * 2560 + bi * BLDNT + bk8];
            bl = &Bsm[(buf * 2 + 1) * 2560 + bi * BLDNT + bk8];
        } else {
            bh = &Bsm[(buf * 2 + 0) * 2560 + bk * BLDNN + bn8];
            bl = &Bsm[(buf * 2 + 1) * 2560 + bk * BLDNN + bn8];
        }
        #pragma unroll
        for (int u = 0; u < 4; u++) {
            float x = (&fb0.x)[u];
            float h = tf32_hi(x);
            bh[u] = h; bl[u] = tf32_hi(x - h);
            float y = (&fb1.x)[u];
            float g = tf32_hi(y);
            bh[4 + u] = g; bl[4 + u] = tf32_hi(y - g);
        }
    };

    // prologue
    fetch(0);
    commit(0);
    __syncthreads();

    wmma::fragment<wmma::accumulator, 16, 16, 8, float> acc[2][2];
    #pragma unroll
    for (int i = 0; i < 2; i++)
        #pragma unroll
        for (int j = 0; j < 2; j++)
            wmma::fill_fragment(acc[i][j], 0.0f);

    for (int k0 = 0; k0 < nk; k0++) {
        int buf = k0 & 1;
        if (k0 + 1 < nk) fetch(k0 + 1);
        #pragma unroll
        for (int k2 = 0; k2 < 2; k2++) {
            wmma::fragment<wmma::matrix_a, 16, 16, 8, wmma::precision::tf32,
                           wmma::row_major> ah0, ah1, al0, al1;
            const float* abase_h = &Asm[(buf * 2 + 0) * 1280 + k2 * 8];
            const float* abase_l = &Asm[(buf * 2 + 1) * 1280 + k2 * 8];
            wmma::load_matrix_sync(ah0, abase_h + (m0 +  0) * ALD, ALD);
            wmma::load_matrix_sync(ah1, abase_h + (m0 + 16) * ALD, ALD);
            wmma::load_matrix_sync(al0, abase_l + (m0 +  0) * ALD, ALD);
            wmma::load_matrix_sync(al1, abase_l + (m0 + 16) * ALD, ALD);
            if (NT) {
                wmma::fragment<wmma::matrix_b, 16, 16, 8, wmma::precision::tf32,
                               wmma::col_major> bh0, bh1, bl0, bl1;
                const float* bbase_h = &Bsm[(buf * 2 + 0) * 2560 + k2 * 8];
                const float* bbase_l = &Bsm[(buf * 2 + 1) * 2560 + k2 * 8];
                wmma::load_matrix_sync(bh0, bbase_h + (n0 +  0) * BLDNT, BLDNT);
                wmma::load_matrix_sync(bh1, bbase_h + (n0 + 16) * BLDNT, BLDNT);
                wmma::load_matrix_sync(bl0, bbase_l + (n0 +  0) * BLDNT, BLDNT);
                wmma::load_matrix_sync(bl1, bbase_l + (n0 + 16) * BLDNT, BLDNT);
                wmma::mma_sync(acc[0][0], ah0, bh0, acc[0][0]);
                wmma::mma_sync(acc[0][1], ah0, bh1, acc[0][1]);
                wmma::mma_sync(acc[1][0], ah1, bh0, acc[1][0]);
                wmma::mma_sync(acc[1][1], ah1, bh1, acc[1][1]);
                wmma::mma_sync(acc[0][0], ah0, bl0, acc[0][0]);
                wmma::mma_sync(acc[0][1], ah0, bl1, acc[0][1]);
                wmma::mma_sync(acc[1][0], ah1, bl0, acc[1][0]);
                wmma::mma_sync(acc[1][1], ah1, bl1, acc[1][1]);
                wmma::mma_sync(acc[0][0], al0, bh0, acc[0][0]);
                wmma::mma_sync(acc[0][1], al0, bh1, acc[0][1]);
                wmma::mma_sync(acc[1][0], al1, bh0, acc[1][0]);
                wmma::mma_sync(acc[1][1], al1, bh1, acc[1][1]);
            } else {
                wmma::fragment<wmma::matrix_b, 16, 16, 8, wmma::precision::tf32,
                               wmma::row_major> bh0, bh1, bl0, bl1;
                const float* bbase_h = &Bsm[(buf * 2 + 0) * 2560 + (k2 * 8) * BLDNN];
                const float* bbase_l = &Bsm[(buf * 2 + 1) * 2560 + (k2 * 8) * BLDNN];
                wmma::load_matrix_sync(bh0, bbase_h + n0, BLDNN);
                wmma::load_matrix_sync(bh1, bbase_h + n0 + 16, BLDNN);
                wmma::load_matrix_sync(bl0, bbase_l + n0, BLDNN);
                wmma::load_matrix_sync(bl1, bbase_l + n0 + 16, BLDNN);
                wmma::mma_sync(acc[0][0], ah0, bh0, acc[0][0]);
                wmma::mma_sync(acc[0][1], ah0, bh1, acc[0][1]);
                wmma::mma_sync(acc[1][0], ah1, bh0, acc[1][0]);
                wmma::mma_sync(acc[1][1], ah1, bh1, acc[1][1]);
                wmma::mma_sync(acc[0][0], ah0, bl0, acc[0][0]);
                wmma::mma_sync(acc[0][1], ah0, bl1, acc[0][1]);
                wmma::mma_sync(acc[1][0], ah1, bl0, acc[1][0]);
                wmma::mma_sync(acc[1][1], ah1, bl1, acc[1][1]);
                wmma::mma_sync(acc[0][0], al0, bh0, acc[0][0]);
                wmma::mma_sync(acc[0][1], al0, bh1, acc[0][1]);
                wmma::mma_sync(acc[1][0], al1, bh0, acc[1][0]);
                wmma::mma_sync(acc[1][1], al1, bh1, acc[1][1]);
            }
        }
        if (k0 + 1 < nk) commit(buf ^ 1);
        __syncthreads();
    }

    // epilogue: stage each 16x16 frag, TWO float4s per lane (full coverage;
    // row rr = lane>>1 in 0..15, cols cc and cc+4, cc = (lane&1)*8).
    float* st = &stage[warp * 256];
    int rr = lane >> 1, cc = (lane & 1) << 3;
    #pragma unroll
    for (int i = 0; i < 2; i++)
        #pragma unroll
        for (int j = 0; j < 2; j++) {
            wmma::store_matrix_sync(st, acc[i][j], 16, wmma::mem_row_major);
            __syncwarp();
            int gr = row0 + m0 + 16 * i + rr;
            int gc = col0 + n0 + 16 * j + cc;
            float4 v0 = *(float4*)&st[rr * 16 + cc];
            float4 v1 = *(float4*)&st[rr * 16 + cc + 4];
            if (bias) {
                const float* bp = bias + gc;
                v0.x += bp[0]; v0.y += bp[1]; v0.z += bp[2]; v0.w += bp[3];
                v1.x += bp[4]; v1.y += bp[5]; v1.z += bp[6]; v1.w += bp[7];
            }
            *(float4*)(C + (size_t)gr * ldc + gc) = v0;
            *(float4*)(C + (size_t)gr * ldc + gc + 4) = v1;
            __syncwarp();
        }
}

// ---------------------------------------------------------------------------
// Tiny fused matmuls: M_out[c][n] = sum_k W4[c][k]*Wbot[k][n],
//                     c_out[n]   = sum_k b_in[k]*Wbot[k][n] + b_out[n]
// ---------------------------------------------------------------------------
__global__ void fuse_small(const float* __restrict__ W4, const float* __restrict__ b_in,
                           const float* __restrict__ Wbot, const float* __restrict__ b_out,
                           float* __restrict__ M_out, float* __restrict__ c_out,
                           int K2, int Nout, int ldb) {
    int n = blockIdx.x * blockDim.x + threadIdx.x;
    if (n >= Nout) return;
    float m0 = 0.f, m1 = 0.f, m2 = 0.f, m3 = 0.f, c = 0.f;
    for (int k = 0; k < K2; k++) {
        float w = Wbot[(size_t)k * ldb + n];
        m0 += W4[k] * w;
        m1 += W4[K2 + k] * w;
        m2 += W4[2 * K2 + k] * w;
        m3 += W4[3 * K2 + k] * w;
        c  += b_in[k] * w;
    }
    M_out[n] = m0; M_out[Nout + n] = m1;
    M_out[2 * Nout + n] = m2; M_out[3 * Nout + n] = m3;
    c_out[n] = c + b_out[n];
}

// ---------------------------------------------------------------------------
// Gather text rows for the 2 query positions per batch: Tq[r][512]
// ---------------------------------------------------------------------------
__global__ void build_tq(const int* __restrict__ nt, const float* __restrict__ text_table,
                         float* __restrict__ Tq) {
    int r = blockIdx.x;               // 0..1023 = b*2 + i
    int b = r >> 1, i = r & 1;
    int id = nt[b * Nn + i];
    const float4* src = (const float4*)(text_table + (size_t)id * Ee);
    float4* dst = (float4*)(Tq + (size_t)r * Ee);
    dst[threadIdx.x] = src[threadIdx.x];      // 128 threads x float4 = 512
}

// ---------------------------------------------------------------------------
// Q += pos4 @ Rq + sq (rank-4 + bias epilogue; pos per row from npos)
// ---------------------------------------------------------------------------
__global__ void q_post(float* __restrict__ Q, const int* dummy,
                       const float* __restrict__ npos,
                       const float* __restrict__ Rq, const float* __restrict__ sq) {
    int idx = blockIdx.x * blockDim.x + threadIdx.x;   // over 2^18 float4s
    if (idx >= 2 * Bsz * DM / 4) return;
    int r = idx >> 8;                 // row 0..1023 = b*2+i
    int c4 = (idx & 255) * 4;
    int b = r >> 1, i = r & 1;
    float4 p = *(const float4*)(npos + (size_t)(b * Nn + i) * 4);
    float4 v = *(float4*)(Q + (size_t)r * DM + c4);
    #pragma unroll
    for (int u = 0; u < 4; u++) {
        int c = c4 + u;
        (&v.x)[u] += sq[c] + p.x * Rq[c] + p.y * Rq[DM + c]
                   + p.z * Rq[2 * DM + c] + p.w * Rq[3 * DM + c];
    }
    *(float4*)(Q + (size_t)r * DM + c4) = v;
}

// ---------------------------------------------------------------------------
// Per-(bq,h) score constants via precomputed Rk/s1: one warp per (bq,h).
// ---------------------------------------------------------------------------
__global__ void __launch_bounds__(256) score_consts2(
        const float* __restrict__ Q, const float* __restrict__ Rk,
        const float* __restrict__ s1, float* __restrict__ r4, float* __restrict__ c0) {
    int warp = threadIdx.x >> 5, lane = threadIdx.x & 31;
    int i = blockIdx.x * 8 + warp;          // 0..8191
    int bq = i >> 3, h = i & 7;
    float4 qv = *(const float4*)(Q + (size_t)bq * DM + h * DEPTH + lane * 4);
    #pragma unroll
    for (int c = 0; c < 5; c++) {
        const float* src = (c < 4) ? (Rk + c * DM) : s1;
        float4 rv = *(const float4*)(src + h * DEPTH + lane * 4);
        float s = qv.x * rv.x + qv.y * rv.y + qv.z * rv.z + qv.w * rv.w;
        #pragma unroll
        for (int off = 16; off; off >>= 1) s += __shfl_xor_sync(0xffffffffu, s, off);
        if (lane == 0) {
            if (c < 4) r4[i * 4 + c] = s;
            else       c0[i] = s;
        }
    }
}

// ---------------------------------------------------------------------------
// Fused attention: scores (gather-dot) -> softmax -> xbar (gather-axpy).
// ---------------------------------------------------------------------------
#define ATTN_SMEM (13736 * 4)

__global__ void __launch_bounds__(256) attn_fused(
        const int* __restrict__ nt, const float* __restrict__ npos,
        const float* __restrict__ U, const float* __restrict__ r4,
        const float* __restrict__ c0, const float* __restrict__ text_table,
        float* __restrict__ xbar, float* __restrict__ wpos) {
    extern __shared__ float dyn[];
    float* sUt  = dyn;                  // [512][16] transposed u_top
    float* sT   = dyn + 8192;           // [100][33]
    float* sS   = dyn + 11492;          // [16][104]
    float* spos = dyn + 13156;          // [100][4]
    float* sr4  = dyn + 13556;          // [16][4]
    float* sc0  = dyn + 13620;          // [16]
    int*   sid  = (int*)(dyn + 13636);  // [100]

    int b = blockIdx.x, tid = threadIdx.x;
    int warp = tid >> 5, lane = tid & 31;

    for (int n = tid; n < Nn; n += 256) {
        int id = nt[b * Nn + n];
        sid[n] = id;
        float4 p = *(const float4*)(npos + (size_t)(b * Nn + n) * 4);
        spos[n * 4 + 0] = p.x; spos[n * 4 + 1] = p.y;
        spos[n * 4 + 2] = p.z; spos[n * 4 + 3] = p.w;
    }
    for (int idx = tid; idx < 16 * Ee; idx += 256) {
        int qh = idx >> 9, d = idx & 511;
        sUt[d * 16 + qh] = U[((size_t)b * 16 + qh) * Ee + d];
    }
    for (int idx = tid; idx < 64; idx += 256) sr4[idx] = r4[(size_t)b * 64 + idx];
    if (tid < 16) sc0[tid] = c0[(size_t)b * 16 + tid];
    __syncthreads();

    float m0 = (sid[0] == 0) ? 1.f : 0.f;
    float m1 = (sid[1] == 0) ? 1.f : 0.f;
    const float scale = 0.08838834764831845f;   // 1/sqrt(128)

    bool active = tid < 200;
    int qh0 = (tid & 7) * 2;
    int n0 = (tid >> 3) * 4;
    float acc[2][4] = {};

    for (int kc = 0; kc < 16; kc++) {
        for (int idx = tid; idx < Nn * 32; idx += 256) {
            int n = idx >> 5, d = idx & 31;
            sT[n * 33 + d] = text_table[(size_t)sid[n] * Ee + kc * 32 + d];
        }
        __syncthreads();
        if (active) {
            #pragma unroll
            for (int d = 0; d < 32; d++) {
                int gd = kc * 32 + d;
                float2 u2 = *(float2*)&sUt[gd * 16 + qh0];
                #pragma unroll
                for (int i = 0; i < 4; i++) {
                    float t = sT[(n0 + i) * 33 + d];
                    acc[0][i] += u2.x * t;
                    acc[1][i] += u2.y * t;
                }
            }
        }
        __syncthreads();
    }
    if (active) {
        #pragma unroll
        for (int j = 0; j < 2; j++) {
            int qh = qh0 + j;
            float mq = (qh < 8) ? m0 : m1;
            #pragma unroll
            for (int i = 0; i < 4; i++) {
                int n = n0 + i;
                float s = acc[j][i]
                        + spos[n * 4 + 0] * sr4[qh * 4 + 0]
                        + spos[n * 4 + 1] * sr4[qh * 4 + 1]
                        + spos[n * 4 + 2] * sr4[qh * 4 + 2]
                        + spos[n * 4 + 3] * sr4[qh * 4 + 3]
                        + sc0[qh];
                float mn = (sid[n] == 0) ? 1.f : 0.f;
                sS[qh * 104 + n] = s * scale + mq * mn * (-1e9f);
            }
        }
    }
    __syncthreads();

    for (int r = warp; r < 16; r += 8) {
        float* row = sS + r * 104;
        float mx = -1e30f;
        for (int jn = lane; jn < Nn; jn += 32) mx = fmaxf(mx, row[jn]);
        #pragma unroll
        for (int off = 16; off; off >>= 1)
            mx = fmaxf(mx, __shfl_xor_sync(0xffffffffu, mx, off));
        float ev[4]; int cnt = 0; float sum = 0.f;
        for (int jn = lane; jn < Nn; jn += 32) {
            float e = expf(row[jn] - mx);
            ev[cnt++] = e; sum += e;
        }
        #pragma unroll
        for (int off = 16; off; off >>= 1)
            sum += __shfl_xor_sync(0xffffffffu, sum, off);
        float inv = 1.f / sum;
        cnt = 0;
        for (int jn = lane; jn < Nn; jn += 32) row[jn] = ev[cnt++] * inv;
    }
    __syncthreads();

    if (tid < 64) {
        int qh = tid >> 2, c = tid & 3;
        float s = 0.f;
        for (int n = 0; n < Nn; n++) s += sS[qh * 104 + n] * spos[n * 4 + c];
        wpos[((size_t)b * 16 + qh) * 4 + c] = s;
    }

    float* sT2 = dyn;                   // reuse [16][512]
    int qh = tid & 15, dg = tid >> 4;
    float xa[32] = {};
    for (int nc = 0; nc < 7; nc++) {
        __syncthreads();
        for (int idx = tid; idx < 16 * Ee; idx += 256) {
            int rr = idx >> 9, d = idx & 511;
            int n = nc * 16 + rr;
            if (n < Nn) sT2[rr * Ee + d] = text_table[(size_t)sid[n] * Ee + d];
        }
        __syncthreads();
        int nmax = min(16, Nn - nc * 16);
        for (int rr = 0; rr < nmax; rr++) {
            float w = sS[qh * 104 + nc * 16 + rr];
            const float* tp = sT2 + rr * Ee + dg;
            #pragma unroll
            for (int j = 0; j < 32; j++) xa[j] += w * tp[16 * j];
        }
    }
    __syncthreads();
    float* sX = dyn;
    #pragma unroll
    for (int j = 0; j < 32; j++) sX[qh * Ee + dg + 16 * j] = xa[j];
    __syncthreads();
    for (int idx = tid; idx < 16 * Ee; idx += 256) {
        int q2 = idx >> 9, d = idx & 511;
        xbar[((size_t)b * 16 + q2) * Ee + d] = sX[idx];
    }
}

// ---------------------------------------------------------------------------
// att += wpos @ Mv + cv (elementwise epilogue, vectorized)
// ---------------------------------------------------------------------------
__global__ void att_post(float* __restrict__ att, const float* __restrict__ wpos,
                         const float* __restrict__ Mv, const float* __restrict__ cv) {
    int idx = blockIdx.x * blockDim.x + threadIdx.x;
    if (idx >= 2 * Bsz * DM / 4) return;
    int r = idx >> 8;
    int c4 = (idx & 255) * 4;
    int z = c4 >> 7;
    const float* wp = wpos + ((size_t)r * 8 + z) * 4;
    float w0 = wp[0], w1 = wp[1], w2 = wp[2], w3 = wp[3];
    float4 v = *(float4*)(att + (size_t)r * DM + c4);
    #pragma unroll
    for (int u = 0; u < 4; u++) {
        int c = c4 + u;
        (&v.x)[u] += cv[c] + w0 * Mv[c] + w1 * Mv[DM + c]
                   + w2 * Mv[2 * DM + c] + w3 * Mv[3 * DM + c];
    }
    *(float4*)(att + (size_t)r * DM + c4) = v;
}

// ---------------------------------------------------------------------------
__global__ void __launch_bounds__(128) cosine_kernel(
        const float* __restrict__ enc, const float* __restrict__ cand_pos,
        const float* __restrict__ Mc, const int* __restrict__ field_id,
        const float* __restrict__ field_table, float* __restrict__ out) {
    __shared__ float red[3][4];
    int b = blockIdx.x, t = threadIdx.x;
    int warp = t >> 5, lane = t & 31;
    const float* fp = field_table + (size_t)field_id[b] * Ee;
    float4 cp = *(const float4*)(cand_pos + (size_t)b * 4);
    float na = 0.f, nb = 0.f, dp = 0.f;
    for (int j = t; j < Ee; j += 128) {
        float e = enc[(size_t)b * Ee + j]
                + cp.x * Mc[j] + cp.y * Mc[Ee + j]
                + cp.z * Mc[2 * Ee + j] + cp.w * Mc[3 * Ee + j];
        float f = fp[j];
        na += e * e; nb += f * f; dp += e * f;
    }
    #pragma unroll
    for (int off = 16; off; off >>= 1) {
        na += __shfl_xor_sync(0xffffffffu, na, off);
        nb += __shfl_xor_sync(0xffffffffu, nb, off);
        dp += __shfl_xor_sync(0xffffffffu, dp, off);
    }
    if (lane == 0) { red[0][warp] = na; red[1][warp] = nb; red[2][warp] = dp; }
    __syncthreads();
    if (t == 0) {
        na = red[0][0] + red[0][1] + red[0][2] + red[0][3];
        nb = red[1][0] + red[1][1] + red[1][2] + red[1][3];
        dp = red[2][0] + red[2][1] + red[2][2] + red[2][3];
        out[b] = -dp * rsqrtf(fmaxf(na, 1e-12f)) * rsqrtf(fmaxf(nb, 1e-12f));
    }
}

// ---------------------------------------------------------------------------
extern "C" void kernel_launch(void* const* d_in, const int* in_sizes, int n_in,
                              void* d_out, int out_size) {
    const int*   field_id   = (const int*)  d_in[0];
    const float* cand_pos   = (const float*)d_in[1];
    const int*   nt         = (const int*)  d_in[2];
    const float* npos       = (const float*)d_in[3];
    const float* text_table = (const float*)d_in[4];
    const float* field_tab  = (const float*)d_in[5];
    const float* cand_W     = (const float*)d_in[6];
    const float* cand_b     = (const float*)d_in[7];
    const float* pos_W      = (const float*)d_in[8];
    const float* pos_b      = (const float*)d_in[9];
    const float* Wq         = (const float*)d_in[10];
    const float* bq         = (const float*)d_in[11];
    const float* Wk         = (const float*)d_in[12];
    const float* bk         = (const float*)d_in[13];
    const float* Wv         = (const float*)d_in[14];
    const float* bv         = (const float*)d_in[15];
    const float* Wo         = (const float*)d_in[16];
    const float* bo         = (const float*)d_in[17];
    const float* proj_W     = (const float*)d_in[18];
    const float* proj_b     = (const float*)d_in[19];
    float* out = (float*)d_out;

    float *Tq, *Qb, *Ub, *r4b, *c0b, *xbarb, *wposb, *attb, *Ob, *encb;
    float *Mvp, *cvp, *Mcp, *ccp, *Rkp, *s1p, *Rqp, *sqp;
    cudaGetSymbolAddress((void**)&Tq,    g_Tq);
    cudaGetSymbolAddress((void**)&Qb,    g_Q);
    cudaGetSymbolAddress((void**)&Ub,    g_U);
    cudaGetSymbolAddress((void**)&r4b,   g_r4);
    cudaGetSymbolAddress((void**)&c0b,   g_c0);
    cudaGetSymbolAddress((void**)&xbarb, g_xbar);
    cudaGetSymbolAddress((void**)&wposb, g_wpos);
    cudaGetSymbolAddress((void**)&attb,  g_att);
    cudaGetSymbolAddress((void**)&Ob,    g_O);
    cudaGetSymbolAddress((void**)&encb,  g_enc);
    cudaGetSymbolAddress((void**)&Mvp,   g_Mv);
    cudaGetSymbolAddress((void**)&cvp,   g_cv);
    cudaGetSymbolAddress((void**)&Mcp,   g_Mc);
    cudaGetSymbolAddress((void**)&ccp,   g_cc);
    cudaGetSymbolAddress((void**)&Rkp,   g_Rk);
    cudaGetSymbolAddress((void**)&s1p,   g_s1);
    cudaGetSymbolAddress((void**)&Rqp,   g_Rq);
    cudaGetSymbolAddress((void**)&sqp,   g_sq);

    cudaFuncSetAttribute(attn_fused,
                         cudaFuncAttributeMaxDynamicSharedMemorySize, ATTN_SMEM);
    cudaFuncSetAttribute(wmma_gemm2<false, false>,
                         cudaFuncAttributeMaxDynamicSharedMemorySize, GSMEM_BYTES);
    cudaFuncSetAttribute(wmma_gemm2<true, false>,
                         cudaFuncAttributeMaxDynamicSharedMemorySize, GSMEM_BYTES);
    cudaFuncSetAttribute(wmma_gemm2<false, true>,
                         cudaFuncAttributeMaxDynamicSharedMemorySize, GSMEM_BYTES);

    // rank-4 folds
    fuse_small<<<4, 256>>>(pos_W, pos_b, Wv + (size_t)Ee * DM, bv, Mvp, cvp, Ee, DM, DM);
    fuse_small<<<2, 256>>>(cand_W, cand_b, proj_W, proj_b, Mcp, ccp, Ee, Ee, Ee);
    fuse_small<<<4, 256>>>(pos_W, pos_b, Wk + (size_t)Ee * DM, bk, Rkp, s1p, Ee, DM, DM);
    fuse_small<<<4, 256>>>(pos_W, pos_b, Wq + (size_t)Ee * DM, bq, Rqp, sqp, Ee, DM, DM);

    // gather text rows for q positions
    build_tq<<<2 * Bsz, 128>>>(nt, text_table, Tq);

    // Q = Tq @ Wq_top  (1024 x 1024 x 512) + rank-4 epilogue
    wmma_gemm2<false, false><<<dim3(8, 16, 1), 256, GSMEM_BYTES>>>(
        Tq, Ee, 0, Wq, DM, 0, Qb, DM, 0, nullptr, Ee);
    q_post<<<(2 * Bsz * DM / 4 + 255) / 256, 256>>>(Qb, nullptr, npos, Rqp, sqp);

    // U_top[(bq)*8+h][i<512] = q_h @ Wk_top_h^T  (8 x [1024 x 512 x 128] NT)
    wmma_gemm2<true, false><<<dim3(4, 16, 8), 256, GSMEM_BYTES>>>(
        Qb, DM, 128, Wk, DM, 128, Ub, 8 * Ee, Ee, nullptr, DEPTH);

    // per-(bq,h) score constants from Rk/s1
    score_consts2<<<16 * Bsz / 8, 256>>>(Qb, Rkp, s1p, r4b, c0b);

    // fused gather-scores -> softmax -> xbar/wpos
    attn_fused<<<Bsz, 256, ATTN_SMEM>>>(nt, npos, Ub, r4b, c0b, text_table,
                                        xbarb, wposb);

    // att = xbar @ Wv_top  (8 x [1024 x 128 x 512], batched via z)
    wmma_gemm2<false, false><<<dim3(1, 16, 8), 256, GSMEM_BYTES>>>(
        xbarb, 8 * Ee, Ee, Wv, DM, 128, attb, DM, 128, nullptr, Ee);
    // att += wpos @ Mv + cv
    att_post<<<(2 * Bsz * DM / 4 + 255) / 256, 256>>>(attb, wposb, Mvp, cvp);

    // O = att @ Wo + bo  (1024 x 1024 x 1024)
    wmma_gemm2<false, false><<<dim3(8, 16, 1), 256, GSMEM_BYTES>>>(
        attb, DM, 0, Wo, DM, 0, Ob, DM, 0, bo, DM);

    // enc = max-pool(O rows 2b,2b+1) @ proj_W[512:,:] + cc   (pool fused)
    wmma_gemm2<false, true><<<dim3(4, 8, 1), 256, GSMEM_BYTES>>>(
        Ob, DM, 0, proj_W + (size_t)Ee * Ee, Ee, 0, encb, Ee, 0, ccp, DM);

    // cosine loss
    cosine_kernel<<<Bsz, 128>>>(encb, cand_pos, Mcp, field_id, field_tab, out);
}

// round 12
// speedup vs baseline: 2.4817x; 2.0628x over previous
#include <cuda_runtime.h>
#include <mma.h>
#include <cstdint>

using namespace nvcuda;

// ---------------------------------------------------------------------------
// Model_57183194578962 — fused neighbor-attention + cosine loss
// B=512, N=100, E=512, D_MODEL=1024, H=8, DEPTH=128, VOCAB=50000
//
// Round 11: rank-4 fold kernels parallelized (split-K + atomics) — they were
// 4 x 233us on 4 SMs (57% of runtime). GEMMs stay on tf32-split wmma v2.
// ---------------------------------------------------------------------------

#define Bsz 512
#define Nn  100
#define Ee  512
#define DM  1024
#define Hh  8
#define DEPTH 128

// ------------------------- static scratch ----------------------------------
__device__ float g_Tq[2 * Bsz * Ee];         // gathered text rows for q   [1024,512]
__device__ float g_Q [2 * Bsz * DM];
__device__ float g_U [16 * Bsz * Ee];        // u_top  [(bq)*8+h][512]
__device__ float g_r4[16 * Bsz * 4];
__device__ float g_c0[16 * Bsz];
__device__ float g_xbar[16 * Bsz * Ee];
__device__ float g_wpos[16 * Bsz * 4];
__device__ float g_att[2 * Bsz * DM];
__device__ float g_O [2 * Bsz * DM];
__device__ float g_enc[Bsz * Ee];
__device__ float g_Mv[4 * DM], g_cv[DM];
__device__ float g_Mc[4 * Ee], g_cc[Ee];
__device__ float g_Rk[4 * DM], g_s1[DM];
__device__ float g_Rq[4 * DM], g_sq[DM];

// ---------------------------------------------------------------------------
// WMMA tf32 split GEMM engine v2 (unchanged from round 10).
// ---------------------------------------------------------------------------
#define ALD 20
#define BLDNN 136
#define BLDNT 20
#define GSMEM_BYTES (17408 * 4)

__device__ __forceinline__ float tf32_hi(float x) { return wmma::__float_to_tf32(x); }

template<bool NT, bool POOL>
__global__ void __launch_bounds__(256) wmma_gemm2(
        const float* __restrict__ A0, int lda, long az,
        const float* __restrict__ B0, int ldb, long bz,
        float* __restrict__ C0, int ldc, long cz,
        const float* __restrict__ bias, int K) {
    const float* A = A0 + (size_t)blockIdx.z * az;
    const float* B = B0 + (size_t)blockIdx.z * bz;
    float*       C = C0 + (size_t)blockIdx.z * cz;

    extern __shared__ float dynsm[];
    float* Asm   = dynsm;
    float* Bsm   = dynsm + 5120;
    float* stage = dynsm + 15360;

    int tid = threadIdx.x;
    int warp = tid >> 5, lane = tid & 31;
    int row0 = blockIdx.y * 64, col0 = blockIdx.x * 128;
    int wm = warp >> 2, wn = warp & 3;
    int m0 = wm * 32, n0 = wn * 32;

    int arr = tid >> 2, ak4 = (tid & 3) << 2;           // A: 64 x 16
    int bk  = tid >> 4, bn8 = (tid & 15) << 3;          // B NN: 16 x 128
    int bi  = tid >> 1, bk8 = (tid & 1) << 3;           // B NT: 128 x 16

    const int nk = K >> 4;

    float4 fa, fb0, fb1;
    auto fetch = [&](int c) {
        int kb = c << 4;
        if (POOL) {
            float4 x = *(const float4*)(A + (size_t)(2 * (row0 + arr)) * lda + kb + ak4);
            float4 y = *(const float4*)(A + (size_t)(2 * (row0 + arr) + 1) * lda + kb + ak4);
            fa.x = fmaxf(x.x, y.x); fa.y = fmaxf(x.y, y.y);
            fa.z = fmaxf(x.z, y.z); fa.w = fmaxf(x.w, y.w);
        } else {
            fa = *(const float4*)(A + (size_t)(row0 + arr) * lda + kb + ak4);
        }
        if (NT) {
            fb0 = *(const float4*)(B + (size_t)(col0 + bi) * ldb + kb + bk8);
            fb1 = *(const float4*)(B + (size_t)(col0 + bi) * ldb + kb + bk8 + 4);
        } else {
            fb0 = *(const float4*)(B + (size_t)(kb + bk) * ldb + col0 + bn8);
            fb1 = *(const float4*)(B + (size_t)(kb + bk) * ldb + col0 + bn8 + 4);
        }
    };
    auto commit = [&](int buf) {
        float* ah = &Asm[(buf * 2 + 0) * 1280 + arr * ALD + ak4];
        float* al = &Asm[(buf * 2 + 1) * 1280 + arr * ALD + ak4];
        #pragma unroll
        for (int u = 0; u < 4; u++) {
            float x = (&fa.x)[u];
            float h = tf32_hi(x);
            ah[u] = h; al[u] = tf32_hi(x - h);
        }
        float* bh;
        float* bl;
        if (NT) {
            bh = &Bsm[(buf * 2 + 0) * 2560 + bi * BLDNT + bk8];
            bl = &Bsm[(buf * 2 + 1) * 2560 + bi * BLDNT + bk8];
        } else {
            bh = &Bsm[(buf * 2 + 0) * 2560 + bk * BLDNN + bn8];
            bl = &Bsm[(buf * 2 + 1) * 2560 + bk * BLDNN + bn8];
        }
        #pragma unroll
        for (int u = 0; u < 4; u++) {
            float x = (&fb0.x)[u];
            float h = tf32_hi(x);
            bh[u] = h; bl[u] = tf32_hi(x - h);
            float y = (&fb1.x)[u];
            float g = tf32_hi(y);
            bh[4 + u] = g; bl[4 + u] = tf32_hi(y - g);
        }
    };

    fetch(0);
    commit(0);
    __syncthreads();

    wmma::fragment<wmma::accumulator, 16, 16, 8, float> acc[2][2];
    #pragma unroll
    for (int i = 0; i < 2; i++)
        #pragma unroll
        for (int j = 0; j < 2; j++)
            wmma::fill_fragment(acc[i][j], 0.0f);

    for (int k0 = 0; k0 < nk; k0++) {
        int buf = k0 & 1;
        if (k0 + 1 < nk) fetch(k0 + 1);
        #pragma unroll
        for (int k2 = 0; k2 < 2; k2++) {
            wmma::fragment<wmma::matrix_a, 16, 16, 8, wmma::precision::tf32,
                           wmma::row_major> ah0, ah1, al0, al1;
            const float* abase_h = &Asm[(buf * 2 + 0) * 1280 + k2 * 8];
            const float* abase_l = &Asm[(buf * 2 + 1) * 1280 + k2 * 8];
            wmma::load_matrix_sync(ah0, abase_h + (m0 +  0) * ALD, ALD);
            wmma::load_matrix_sync(ah1, abase_h + (m0 + 16) * ALD, ALD);
            wmma::load_matrix_sync(al0, abase_l + (m0 +  0) * ALD, ALD);
            wmma::load_matrix_sync(al1, abase_l + (m0 + 16) * ALD, ALD);
            if (NT) {
                wmma::fragment<wmma::matrix_b, 16, 16, 8, wmma::precision::tf32,
                               wmma::col_major> bh0, bh1, bl0, bl1;
                const float* bbase_h = &Bsm[(buf * 2 + 0) * 2560 + k2 * 8];
                const float* bbase_l = &Bsm[(buf * 2 + 1) * 2560 + k2 * 8];
                wmma::load_matrix_sync(bh0, bbase_h + (n0 +  0) * BLDNT, BLDNT);
                wmma::load_matrix_sync(bh1, bbase_h + (n0 + 16) * BLDNT, BLDNT);
                wmma::load_matrix_sync(bl0, bbase_l + (n0 +  0) * BLDNT, BLDNT);
                wmma::load_matrix_sync(bl1, bbase_l + (n0 + 16) * BLDNT, BLDNT);
                wmma::mma_sync(acc[0][0], ah0, bh0, acc[0][0]);
                wmma::mma_sync(acc[0][1], ah0, bh1, acc[0][1]);
                wmma::mma_sync(acc[1][0], ah1, bh0, acc[1][0]);
                wmma::mma_sync(acc[1][1], ah1, bh1, acc[1][1]);
                wmma::mma_sync(acc[0][0], ah0, bl0, acc[0][0]);
                wmma::mma_sync(acc[0][1], ah0, bl1, acc[0][1]);
                wmma::mma_sync(acc[1][0], ah1, bl0, acc[1][0]);
                wmma::mma_sync(acc[1][1], ah1, bl1, acc[1][1]);
                wmma::mma_sync(acc[0][0], al0, bh0, acc[0][0]);
                wmma::mma_sync(acc[0][1], al0, bh1, acc[0][1]);
                wmma::mma_sync(acc[1][0], al1, bh0, acc[1][0]);
                wmma::mma_sync(acc[1][1], al1, bh1, acc[1][1]);
            } else {
                wmma::fragment<wmma::matrix_b, 16, 16, 8, wmma::precision::tf32,
                               wmma::row_major> bh0, bh1, bl0, bl1;
                const float* bbase_h = &Bsm[(buf * 2 + 0) * 2560 + (k2 * 8) * BLDNN];
                const float* bbase_l = &Bsm[(buf * 2 + 1) * 2560 + (k2 * 8) * BLDNN];
                wmma::load_matrix_sync(bh0, bbase_h + n0, BLDNN);
                wmma::load_matrix_sync(bh1, bbase_h + n0 + 16, BLDNN);
                wmma::load_matrix_sync(bl0, bbase_l + n0, BLDNN);
                wmma::load_matrix_sync(bl1, bbase_l + n0 + 16, BLDNN);
                wmma::mma_sync(acc[0][0], ah0, bh0, acc[0][0]);
                wmma::mma_sync(acc[0][1], ah0, bh1, acc[0][1]);
                wmma::mma_sync(acc[1][0], ah1, bh0, acc[1][0]);
                wmma::mma_sync(acc[1][1], ah1, bh1, acc[1][1]);
                wmma::mma_sync(acc[0][0], ah0, bl0, acc[0][0]);
                wmma::mma_sync(acc[0][1], ah0, bl1, acc[0][1]);
                wmma::mma_sync(acc[1][0], ah1, bl0, acc[1][0]);
                wmma::mma_sync(acc[1][1], ah1, bl1, acc[1][1]);
                wmma::mma_sync(acc[0][0], al0, bh0, acc[0][0]);
                wmma::mma_sync(acc[0][1], al0, bh1, acc[0][1]);
                wmma::mma_sync(acc[1][0], al1, bh0, acc[1][0]);
                wmma::mma_sync(acc[1][1], al1, bh1, acc[1][1]);
            }
        }
        if (k0 + 1 < nk) commit(buf ^ 1);
        __syncthreads();
    }

    float* st = &stage[warp * 256];
    int rr = lane >> 1, cc = (lane & 1) << 3;
    #pragma unroll
    for (int i = 0; i < 2; i++)
        #pragma unroll
        for (int j = 0; j < 2; j++) {
            wmma::store_matrix_sync(st, acc[i][j], 16, wmma::mem_row_major);
            __syncwarp();
            int gr = row0 + m0 + 16 * i + rr;
            int gc = col0 + n0 + 16 * j + cc;
            float4 v0 = *(float4*)&st[rr * 16 + cc];
            float4 v1 = *(float4*)&st[rr * 16 + cc + 4];
            if (bias) {
                const float* bp = bias + gc;
                v0.x += bp[0]; v0.y += bp[1]; v0.z += bp[2]; v0.w += bp[3];
                v1.x += bp[4]; v1.y += bp[5]; v1.z += bp[6]; v1.w += bp[7];
            }
            *(float4*)(C + (size_t)gr * ldc + gc) = v0;
            *(float4*)(C + (size_t)gr * ldc + gc + 4) = v1;
            __syncwarp();
        }
}

// ---------------------------------------------------------------------------
// Rank-4 fold, parallel version.
//   fold_init: M buffers <- 0, c buffers <- their bias vectors.
//   fuse_split: grid (Nout/128, KSPLIT); each thread sums a K-chunk and
//               atomicAdds 5 partials. Coalesced across threads.
// ---------------------------------------------------------------------------
__global__ void fold_init(float* __restrict__ Mv, float* __restrict__ cv,
                          const float* __restrict__ bv,
                          float* __restrict__ Rk, float* __restrict__ s1,
                          const float* __restrict__ bk,
                          float* __restrict__ Rq, float* __restrict__ sq,
                          const float* __restrict__ bq,
                          float* __restrict__ Mc, float* __restrict__ cc,
                          const float* __restrict__ pb) {
    int i = blockIdx.x * blockDim.x + threadIdx.x;
    if (i < 4 * DM) {
        Mv[i] = 0.f; Rk[i] = 0.f; Rq[i] = 0.f;
        if (i < 4 * Ee) Mc[i] = 0.f;
    } else {
        int j = i - 4 * DM;
        if (j < DM) {
            cv[j] = bv[j]; s1[j] = bk[j]; sq[j] = bq[j];
            if (j < Ee) cc[j] = pb[j];
        }
    }
}

__global__ void __launch_bounds__(128) fuse_split(
        const float* __restrict__ W4, const float* __restrict__ b_in,
        const float* __restrict__ Wbot,
        float* __restrict__ M_out, float* __restrict__ c_out,
        int K2, int Nout, int ldb, int ksplit) {
    int n = blockIdx.x * 128 + threadIdx.x;
    if (n >= Nout) return;
    int chunk = K2 / ksplit;
    int k0 = blockIdx.y * chunk, k1 = k0 + chunk;
    float m0 = 0.f, m1 = 0.f, m2 = 0.f, m3 = 0.f, c = 0.f;
    for (int k = k0; k < k1; k++) {
        float w = Wbot[(size_t)k * ldb + n];
        m0 += W4[k] * w;
        m1 += W4[K2 + k] * w;
        m2 += W4[2 * K2 + k] * w;
        m3 += W4[3 * K2 + k] * w;
        c  += b_in[k] * w;
    }
    atomicAdd(&M_out[n], m0);
    atomicAdd(&M_out[Nout + n], m1);
    atomicAdd(&M_out[2 * Nout + n], m2);
    atomicAdd(&M_out[3 * Nout + n], m3);
    atomicAdd(&c_out[n], c);
}

// ---------------------------------------------------------------------------
// Gather text rows for the 2 query positions per batch: Tq[r][512]
// ---------------------------------------------------------------------------
__global__ void build_tq(const int* __restrict__ nt, const float* __restrict__ text_table,
                         float* __restrict__ Tq) {
    int r = blockIdx.x;               // 0..1023 = b*2 + i
    int b = r >> 1, i = r & 1;
    int id = nt[b * Nn + i];
    const float4* src = (const float4*)(text_table + (size_t)id * Ee);
    float4* dst = (float4*)(Tq + (size_t)r * Ee);
    dst[threadIdx.x] = src[threadIdx.x];      // 128 threads x float4 = 512
}

// ---------------------------------------------------------------------------
// Q += pos4 @ Rq + sq (rank-4 + bias epilogue; pos per row from npos)
// ---------------------------------------------------------------------------
__global__ void q_post(float* __restrict__ Q, const int* dummy,
                       const float* __restrict__ npos,
                       const float* __restrict__ Rq, const float* __restrict__ sq) {
    int idx = blockIdx.x * blockDim.x + threadIdx.x;   // over 2^18 float4s
    if (idx >= 2 * Bsz * DM / 4) return;
    int r = idx >> 8;                 // row 0..1023 = b*2+i
    int c4 = (idx & 255) * 4;
    int b = r >> 1, i = r & 1;
    float4 p = *(const float4*)(npos + (size_t)(b * Nn + i) * 4);
    float4 v = *(float4*)(Q + (size_t)r * DM + c4);
    #pragma unroll
    for (int u = 0; u < 4; u++) {
        int c = c4 + u;
        (&v.x)[u] += sq[c] + p.x * Rq[c] + p.y * Rq[DM + c]
                   + p.z * Rq[2 * DM + c] + p.w * Rq[3 * DM + c];
    }
    *(float4*)(Q + (size_t)r * DM + c4) = v;
}

// ---------------------------------------------------------------------------
// Per-(bq,h) score constants via precomputed Rk/s1: one warp per (bq,h).
// ---------------------------------------------------------------------------
__global__ void __launch_bounds__(256) score_consts2(
        const float* __restrict__ Q, const float* __restrict__ Rk,
        const float* __restrict__ s1, float* __restrict__ r4, float* __restrict__ c0) {
    int warp = threadIdx.x >> 5, lane = threadIdx.x & 31;
    int i = blockIdx.x * 8 + warp;          // 0..8191
    int bq = i >> 3, h = i & 7;
    float4 qv = *(const float4*)(Q + (size_t)bq * DM + h * DEPTH + lane * 4);
    #pragma unroll
    for (int c = 0; c < 5; c++) {
        const float* src = (c < 4) ? (Rk + c * DM) : s1;
        float4 rv = *(const float4*)(src + h * DEPTH + lane * 4);
        float s = qv.x * rv.x + qv.y * rv.y + qv.z * rv.z + qv.w * rv.w;
        #pragma unroll
        for (int off = 16; off; off >>= 1) s += __shfl_xor_sync(0xffffffffu, s, off);
        if (lane == 0) {
            if (c < 4) r4[i * 4 + c] = s;
            else       c0[i] = s;
        }
    }
}

// ---------------------------------------------------------------------------
// Fused attention: scores (gather-dot) -> softmax -> xbar (gather-axpy).
// ---------------------------------------------------------------------------
#define ATTN_SMEM (13736 * 4)

__global__ void __launch_bounds__(256) attn_fused(
        const int* __restrict__ nt, const float* __restrict__ npos,
        const float* __restrict__ U, const float* __restrict__ r4,
        const float* __restrict__ c0, const float* __restrict__ text_table,
        float* __restrict__ xbar, float* __restrict__ wpos) {
    extern __shared__ float dyn[];
    float* sUt  = dyn;                  // [512][16] transposed u_top
    float* sT   = dyn + 8192;           // [100][33]
    float* sS   = dyn + 11492;          // [16][104]
    float* spos = dyn + 13156;          // [100][4]
    float* sr4  = dyn + 13556;          // [16][4]
    float* sc0  = dyn + 13620;          // [16]
    int*   sid  = (int*)(dyn + 13636);  // [100]

    int b = blockIdx.x, tid = threadIdx.x;
    int warp = tid >> 5, lane = tid & 31;

    for (int n = tid; n < Nn; n += 256) {
        int id = nt[b * Nn + n];
        sid[n] = id;
        float4 p = *(const float4*)(npos + (size_t)(b * Nn + n) * 4);
        spos[n * 4 + 0] = p.x; spos[n * 4 + 1] = p.y;
        spos[n * 4 + 2] = p.z; spos[n * 4 + 3] = p.w;
    }
    for (int idx = tid; idx < 16 * Ee; idx += 256) {
        int qh = idx >> 9, d = idx & 511;
        sUt[d * 16 + qh] = U[((size_t)b * 16 + qh) * Ee + d];
    }
    for (int idx = tid; idx < 64; idx += 256) sr4[idx] = r4[(size_t)b * 64 + idx];
    if (tid < 16) sc0[tid] = c0[(size_t)b * 16 + tid];
    __syncthreads();

    float m0 = (sid[0] == 0) ? 1.f : 0.f;
    float m1 = (sid[1] == 0) ? 1.f : 0.f;
    const float scale = 0.08838834764831845f;   // 1/sqrt(128)

    bool active = tid < 200;
    int qh0 = (tid & 7) * 2;
    int n0 = (tid >> 3) * 4;
    float acc[2][4] = {};

    for (int kc = 0; kc < 16; kc++) {
        for (int idx = tid; idx < Nn * 32; idx += 256) {
            int n = idx >> 5, d = idx & 31;
            sT[n * 33 + d] = text_table[(size_t)sid[n] * Ee + kc * 32 + d];
        }
        __syncthreads();
        if (active) {
            #pragma unroll
            for (int d = 0; d < 32; d++) {
                int gd = kc * 32 + d;
                float2 u2 = *(float2*)&sUt[gd * 16 + qh0];
                #pragma unroll
                for (int i = 0; i < 4; i++) {
                    float t = sT[(n0 + i) * 33 + d];
                    acc[0][i] += u2.x * t;
                    acc[1][i] += u2.y * t;
                }
            }
        }
        __syncthreads();
    }
    if (active) {
        #pragma unroll
        for (int j = 0; j < 2; j++) {
            int qh = qh0 + j;
            float mq = (qh < 8) ? m0 : m1;
            #pragma unroll
            for (int i = 0; i < 4; i++) {
                int n = n0 + i;
                float s = acc[j][i]
                        + spos[n * 4 + 0] * sr4[qh * 4 + 0]
                        + spos[n * 4 + 1] * sr4[qh * 4 + 1]
                        + spos[n * 4 + 2] * sr4[qh * 4 + 2]
                        + spos[n * 4 + 3] * sr4[qh * 4 + 3]
                        + sc0[qh];
                float mn = (sid[n] == 0) ? 1.f : 0.f;
                sS[qh * 104 + n] = s * scale + mq * mn * (-1e9f);
            }
        }
    }
    __syncthreads();

    for (int r = warp; r < 16; r += 8) {
        float* row = sS + r * 104;
        float mx = -1e30f;
        for (int jn = lane; jn < Nn; jn += 32) mx = fmaxf(mx, row[jn]);
        #pragma unroll
        for (int off = 16; off; off >>= 1)
            mx = fmaxf(mx, __shfl_xor_sync(0xffffffffu, mx, off));
        float ev[4]; int cnt = 0; float sum = 0.f;
        for (int jn = lane; jn < Nn; jn += 32) {
            float e = expf(row[jn] - mx);
            ev[cnt++] = e; sum += e;
        }
        #pragma unroll
        for (int off = 16; off; off >>= 1)
            sum += __shfl_xor_sync(0xffffffffu, sum, off);
        float inv = 1.f / sum;
        cnt = 0;
        for (int jn = lane; jn < Nn; jn += 32) row[jn] = ev[cnt++] * inv;
    }
    __syncthreads();

    if (tid < 64) {
        int qh = tid >> 2, c = tid & 3;
        float s = 0.f;
        for (int n = 0; n < Nn; n++) s += sS[qh * 104 + n] * spos[n * 4 + c];
        wpos[((size_t)b * 16 + qh) * 4 + c] = s;
    }

    float* sT2 = dyn;                   // reuse [16][512]
    int qh = tid & 15, dg = tid >> 4;
    float xa[32] = {};
    for (int nc = 0; nc < 7; nc++) {
        __syncthreads();
        for (int idx = tid; idx < 16 * Ee; idx += 256) {
            int rr = idx >> 9, d = idx & 511;
            int n = nc * 16 + rr;
            if (n < Nn) sT2[rr * Ee + d] = text_table[(size_t)sid[n] * Ee + d];
        }
        __syncthreads();
        int nmax = min(16, Nn - nc * 16);
        for (int rr = 0; rr < nmax; rr++) {
            float w = sS[qh * 104 + nc * 16 + rr];
            const float* tp = sT2 + rr * Ee + dg;
            #pragma unroll
            for (int j = 0; j < 32; j++) xa[j] += w * tp[16 * j];
        }
    }
    __syncthreads();
    float* sX = dyn;
    #pragma unroll
    for (int j = 0; j < 32; j++) sX[qh * Ee + dg + 16 * j] = xa[j];
    __syncthreads();
    for (int idx = tid; idx < 16 * Ee; idx += 256) {
        int q2 = idx >> 9, d = idx & 511;
        xbar[((size_t)b * 16 + q2) * Ee + d] = sX[idx];
    }
}

// ---------------------------------------------------------------------------
// att += wpos @ Mv + cv (elementwise epilogue, vectorized)
// ---------------------------------------------------------------------------
__global__ void att_post(float* __restrict__ att, const float* __restrict__ wpos,
                         const float* __restrict__ Mv, const float* __restrict__ cv) {
    int idx = blockIdx.x * blockDim.x + threadIdx.x;
    if (idx >= 2 * Bsz * DM / 4) return;
    int r = idx >> 8;
    int c4 = (idx & 255) * 4;
    int z = c4 >> 7;
    const float* wp = wpos + ((size_t)r * 8 + z) * 4;
    float w0 = wp[0], w1 = wp[1], w2 = wp[2], w3 = wp[3];
    float4 v = *(float4*)(att + (size_t)r * DM + c4);
    #pragma unroll
    for (int u = 0; u < 4; u++) {
        int c = c4 + u;
        (&v.x)[u] += cv[c] + w0 * Mv[c] + w1 * Mv[DM + c]
                   + w2 * Mv[2 * DM + c] + w3 * Mv[3 * DM + c];
    }
    *(float4*)(att + (size_t)r * DM + c4) = v;
}

// ---------------------------------------------------------------------------
__global__ void __launch_bounds__(128) cosine_kernel(
        const float* __restrict__ enc, const float* __restrict__ cand_pos,
        const float* __restrict__ Mc, const int* __restrict__ field_id,
        const float* __restrict__ field_table, float* __restrict__ out) {
    __shared__ float red[3][4];
    int b = blockIdx.x, t = threadIdx.x;
    int warp = t >> 5, lane = t & 31;
    const float* fp = field_table + (size_t)field_id[b] * Ee;
    float4 cp = *(const float4*)(cand_pos + (size_t)b * 4);
    float na = 0.f, nb = 0.f, dp = 0.f;
    for (int j = t; j < Ee; j += 128) {
        float e = enc[(size_t)b * Ee + j]
                + cp.x * Mc[j] + cp.y * Mc[Ee + j]
                + cp.z * Mc[2 * Ee + j] + cp.w * Mc[3 * Ee + j];
        float f = fp[j];
        na += e * e; nb += f * f; dp += e * f;
    }
    #pragma unroll
    for (int off = 16; off; off >>= 1) {
        na += __shfl_xor_sync(0xffffffffu, na, off);
        nb += __shfl_xor_sync(0xffffffffu, nb, off);
        dp += __shfl_xor_sync(0xffffffffu, dp, off);
    }
    if (lane == 0) { red[0][warp] = na; red[1][warp] = nb; red[2][warp] = dp; }
    __syncthreads();
    if (t == 0) {
        na = red[0][0] + red[0][1] + red[0][2] + red[0][3];
        nb = red[1][0] + red[1][1] + red[1][2] + red[1][3];
        dp = red[2][0] + red[2][1] + red[2][2] + red[2][3];
        out[b] = -dp * rsqrtf(fmaxf(na, 1e-12f)) * rsqrtf(fmaxf(nb, 1e-12f));
    }
}

// ---------------------------------------------------------------------------
extern "C" void kernel_launch(void* const* d_in, const int* in_sizes, int n_in,
                              void* d_out, int out_size) {
    const int*   field_id   = (const int*)  d_in[0];
    const float* cand_pos   = (const float*)d_in[1];
    const int*   nt         = (const int*)  d_in[2];
    const float* npos       = (const float*)d_in[3];
    const float* text_table = (const float*)d_in[4];
    const float* field_tab  = (const float*)d_in[5];
    const float* cand_W     = (const float*)d_in[6];
    const float* cand_b     = (const float*)d_in[7];
    const float* pos_W      = (const float*)d_in[8];
    const float* pos_b      = (const float*)d_in[9];
    const float* Wq         = (const float*)d_in[10];
    const float* bq         = (const float*)d_in[11];
    const float* Wk         = (const float*)d_in[12];
    const float* bk         = (const float*)d_in[13];
    const float* Wv         = (const float*)d_in[14];
    const float* bv         = (const float*)d_in[15];
    const float* Wo         = (const float*)d_in[16];
    const float* bo         = (const float*)d_in[17];
    const float* proj_W     = (const float*)d_in[18];
    const float* proj_b     = (const float*)d_in[19];
    float* out = (float*)d_out;

    float *Tq, *Qb, *Ub, *r4b, *c0b, *xbarb, *wposb, *attb, *Ob, *encb;
    float *Mvp, *cvp, *Mcp, *ccp, *Rkp, *s1p, *Rqp, *sqp;
    cudaGetSymbolAddress((void**)&Tq,    g_Tq);
    cudaGetSymbolAddress((void**)&Qb,    g_Q);
    cudaGetSymbolAddress((void**)&Ub,    g_U);
    cudaGetSymbolAddress((void**)&r4b,   g_r4);
    cudaGetSymbolAddress((void**)&c0b,   g_c0);
    cudaGetSymbolAddress((void**)&xbarb, g_xbar);
    cudaGetSymbolAddress((void**)&wposb, g_wpos);
    cudaGetSymbolAddress((void**)&attb,  g_att);
    cudaGetSymbolAddress((void**)&Ob,    g_O);
    cudaGetSymbolAddress((void**)&encb,  g_enc);
    cudaGetSymbolAddress((void**)&Mvp,   g_Mv);
    cudaGetSymbolAddress((void**)&cvp,   g_cv);
    cudaGetSymbolAddress((void**)&Mcp,   g_Mc);
    cudaGetSymbolAddress((void**)&ccp,   g_cc);
    cudaGetSymbolAddress((void**)&Rkp,   g_Rk);
    cudaGetSymbolAddress((void**)&s1p,   g_s1);
    cudaGetSymbolAddress((void**)&Rqp,   g_Rq);
    cudaGetSymbolAddress((void**)&sqp,   g_sq);

    cudaFuncSetAttribute(attn_fused,
                         cudaFuncAttributeMaxDynamicSharedMemorySize, ATTN_SMEM);
    cudaFuncSetAttribute(wmma_gemm2<false, false>,
                         cudaFuncAttributeMaxDynamicSharedMemorySize, GSMEM_BYTES);
    cudaFuncSetAttribute(wmma_gemm2<true, false>,
                         cudaFuncAttributeMaxDynamicSharedMemorySize, GSMEM_BYTES);
    cudaFuncSetAttribute(wmma_gemm2<false, true>,
                         cudaFuncAttributeMaxDynamicSharedMemorySize, GSMEM_BYTES);

    // ---- rank-4 folds, parallel: init then split-K atomic accumulation ----
    fold_init<<<(5 * DM + 255) / 256, 256>>>(Mvp, cvp, bv, Rkp, s1p, bk,
                                             Rqp, sqp, bq, Mcp, ccp, proj_b);
    fuse_split<<<dim3(DM / 128, 8), 128>>>(pos_W, pos_b, Wv + (size_t)Ee * DM,
                                           Mvp, cvp, Ee, DM, DM, 8);
    fuse_split<<<dim3(DM / 128, 8), 128>>>(pos_W, pos_b, Wk + (size_t)Ee * DM,
                                           Rkp, s1p, Ee, DM, DM, 8);
    fuse_split<<<dim3(DM / 128, 8), 128>>>(pos_W, pos_b, Wq + (size_t)Ee * DM,
                                           Rqp, sqp, Ee, DM, DM, 8);
    fuse_split<<<dim3(Ee / 128, 8), 128>>>(cand_W, cand_b, proj_W,
                                           Mcp, ccp, Ee, Ee, Ee, 8);

    // gather text rows for q positions
    build_tq<<<2 * Bsz, 128>>>(nt, text_table, Tq);

    // Q = Tq @ Wq_top  (1024 x 1024 x 512) + rank-4 epilogue
    wmma_gemm2<false, false><<<dim3(8, 16, 1), 256, GSMEM_BYTES>>>(
        Tq, Ee, 0, Wq, DM, 0, Qb, DM, 0, nullptr, Ee);
    q_post<<<(2 * Bsz * DM / 4 + 255) / 256, 256>>>(Qb, nullptr, npos, Rqp, sqp);

    // U_top[(bq)*8+h][i<512] = q_h @ Wk_top_h^T  (8 x [1024 x 512 x 128] NT)
    wmma_gemm2<true, false><<<dim3(4, 16, 8), 256, GSMEM_BYTES>>>(
        Qb, DM, 128, Wk, DM, 128, Ub, 8 * Ee, Ee, nullptr, DEPTH);

    // per-(bq,h) score constants from Rk/s1
    score_consts2<<<16 * Bsz / 8, 256>>>(Qb, Rkp, s1p, r4b, c0b);

    // fused gather-scores -> softmax -> xbar/wpos
    attn_fused<<<Bsz, 256, ATTN_SMEM>>>(nt, npos, Ub, r4b, c0b, text_table,
                                        xbarb, wposb);

    // att = xbar @ Wv_top  (8 x [1024 x 128 x 512], batched via z)
    wmma_gemm2<false, false><<<dim3(1, 16, 8), 256, GSMEM_BYTES>>>(
        xbarb, 8 * Ee, Ee, Wv, DM, 128, attb, DM, 128, nullptr, Ee);
    // att += wpos @ Mv + cv
    att_post<<<(2 * Bsz * DM / 4 + 255) / 256, 256>>>(attb, wposb, Mvp, cvp);

    // O = att @ Wo + bo  (1024 x 1024 x 1024)
    wmma_gemm2<false, false><<<dim3(8, 16, 1), 256, GSMEM_BYTES>>>(
        attb, DM, 0, Wo, DM, 0, Ob, DM, 0, bo, DM);

    // enc = max-pool(O rows 2b,2b+1) @ proj_W[512:,:] + cc   (pool fused)
    wmma_gemm2<false, true><<<dim3(4, 8, 1), 256, GSMEM_BYTES>>>(
        Ob, DM, 0, proj_W + (size_t)Ee * Ee, Ee, 0, encb, Ee, 0, ccp, DM);

    // cosine loss
    cosine_kernel<<<Bsz, 128>>>(encb, cand_pos, Mcp, field_id, field_tab, out);
}

// round 14
// speedup vs baseline: 3.8455x; 1.5495x over previous
#include <cuda_runtime.h>
#include <cuda_bf16.h>
#include <mma.h>
#include <cstdint>

using namespace nvcuda;

// ---------------------------------------------------------------------------
// Model_57183194578962 — fused neighbor-attention + cosine loss
// B=512, N=100, E=512, D_MODEL=1024, H=8, DEPTH=128, VOCAB=50000
//
// Round 13 == Round 12 resubmitted (infra failure, never measured):
// bf16-k16 split GEMM engine (2x MACs/inst, half smem); merged fold launch.
// ---------------------------------------------------------------------------

#define Bsz 512
#define Nn  100
#define Ee  512
#define DM  1024
#define Hh  8
#define DEPTH 128

// ------------------------- static scratch ----------------------------------
__device__ float g_Tq[2 * Bsz * Ee];
__device__ float g_Q [2 * Bsz * DM];
__device__ float g_U [16 * Bsz * Ee];
__device__ float g_r4[16 * Bsz * 4];
__device__ float g_c0[16 * Bsz];
__device__ float g_xbar[16 * Bsz * Ee];
__device__ float g_wpos[16 * Bsz * 4];
__device__ float g_att[2 * Bsz * DM];
__device__ float g_O [2 * Bsz * DM];
__device__ float g_enc[Bsz * Ee];
__device__ float g_Mv[4 * DM], g_cv[DM];
__device__ float g_Mc[4 * Ee], g_cc[Ee];
__device__ float g_Rk[4 * DM], g_s1[DM];
__device__ float g_Rq[4 * DM], g_sq[DM];

// ---------------------------------------------------------------------------
// WMMA bf16 split GEMM engine v3.
//   C = A @ B (+bias). CTA 64(M) x 128(N), k-chunk 16, double buffered.
//   hi/lo bf16 tiles resident; 3 passes (hh + hl + lh) == fp32 to ~2^-16.
//   m16n16k16 -> 12 MMAs per warp per chunk.
//   NT: B[n][k] row-major source. POOL: A row m = max(Asrc[2m], Asrc[2m+1]).
// smem layout (bytes):
//   Asm  [buf*2+hl]*1536 bf16  (64 x 24)         [0, 12288)
//   Bsm  [buf*2+hl]*3072 bf16                    [12288, 36864)
//   stage 8 warps x 256 float                    [36864, 45056)
// ---------------------------------------------------------------------------
#define ALD 24
#define BLDNN 136
#define BLDNT 24
#define A_COPY 1536
#define B_COPY 3072
#define GSMEM_BYTES 45056

template<bool NT, bool POOL>
__global__ void __launch_bounds__(256) wmma_gemm3(
        const float* __restrict__ A0, int lda, long az,
        const float* __restrict__ B0, int ldb, long bz,
        float* __restrict__ C0, int ldc, long cz,
        const float* __restrict__ bias, int K) {
    const float* A = A0 + (size_t)blockIdx.z * az;
    const float* B = B0 + (size_t)blockIdx.z * bz;
    float*       C = C0 + (size_t)blockIdx.z * cz;

    extern __shared__ char smraw[];
    __nv_bfloat16* Asm = (__nv_bfloat16*)smraw;
    __nv_bfloat16* Bsm = (__nv_bfloat16*)(smraw + 12288);
    float* stage = (float*)(smraw + 36864);

    int tid = threadIdx.x;
    int warp = tid >> 5, lane = tid & 31;
    int row0 = blockIdx.y * 64, col0 = blockIdx.x * 128;
    int wm = warp >> 2, wn = warp & 3;
    int m0 = wm * 32, n0 = wn * 32;

    int arr = tid >> 2, ak4 = (tid & 3) << 2;           // A: 64 x 16
    int bk  = tid >> 4, bn8 = (tid & 15) << 3;          // B NN: 16 x 128
    int bi  = tid >> 1, bk8 = (tid & 1) << 3;           // B NT: 128 x 16

    const int nk = K >> 4;

    float4 fa, fb0, fb1;
    auto fetch = [&](int c) {
        int kb = c << 4;
        if (POOL) {
            float4 x = *(const float4*)(A + (size_t)(2 * (row0 + arr)) * lda + kb + ak4);
            float4 y = *(const float4*)(A + (size_t)(2 * (row0 + arr) + 1) * lda + kb + ak4);
            fa.x = fmaxf(x.x, y.x); fa.y = fmaxf(x.y, y.y);
            fa.z = fmaxf(x.z, y.z); fa.w = fmaxf(x.w, y.w);
        } else {
            fa = *(const float4*)(A + (size_t)(row0 + arr) * lda + kb + ak4);
        }
        if (NT) {
            fb0 = *(const float4*)(B + (size_t)(col0 + bi) * ldb + kb + bk8);
            fb1 = *(const float4*)(B + (size_t)(col0 + bi) * ldb + kb + bk8 + 4);
        } else {
            fb0 = *(const float4*)(B + (size_t)(kb + bk) * ldb + col0 + bn8);
            fb1 = *(const float4*)(B + (size_t)(kb + bk) * ldb + col0 + bn8 + 4);
        }
    };
    auto commit = [&](int buf) {
        __nv_bfloat16* ah = Asm + (buf * 2 + 0) * A_COPY + arr * ALD + ak4;
        __nv_bfloat16* al = Asm + (buf * 2 + 1) * A_COPY + arr * ALD + ak4;
        #pragma unroll
        for (int u = 0; u < 4; u++) {
            float x = (&fa.x)[u];
            __nv_bfloat16 h = __float2bfloat16(x);
            ah[u] = h;
            al[u] = __float2bfloat16(x - __bfloat162float(h));
        }
        __nv_bfloat16 *bh, *bl;
        if (NT) {
            bh = Bsm + (buf * 2 + 0) * B_COPY + bi * BLDNT + bk8;
            bl = Bsm + (buf * 2 + 1) * B_COPY + bi * BLDNT + bk8;
        } else {
            bh = Bsm + (buf * 2 + 0) * B_COPY + bk * BLDNN + bn8;
            bl = Bsm + (buf * 2 + 1) * B_COPY + bk * BLDNN + bn8;
        }
        #pragma unroll
        for (int u = 0; u < 4; u++) {
            float x = (&fb0.x)[u];
            __nv_bfloat16 h = __float2bfloat16(x);
            bh[u] = h;
            bl[u] = __float2bfloat16(x - __bfloat162float(h));
            float y = (&fb1.x)[u];
            __nv_bfloat16 g = __float2bfloat16(y);
            bh[4 + u] = g;
            bl[4 + u] = __float2bfloat16(y - __bfloat162float(g));
        }
    };

    fetch(0);
    commit(0);
    __syncthreads();

    wmma::fragment<wmma::accumulator, 16, 16, 16, float> acc[2][2];
    #pragma unroll
    for (int i = 0; i < 2; i++)
        #pragma unroll
        for (int j = 0; j < 2; j++)
            wmma::fill_fragment(acc[i][j], 0.0f);

    for (int k0 = 0; k0 < nk; k0++) {
        int buf = k0 & 1;
        if (k0 + 1 < nk) fetch(k0 + 1);

        wmma::fragment<wmma::matrix_a, 16, 16, 16, __nv_bfloat16,
                       wmma::row_major> ah0, ah1, al0, al1;
        const __nv_bfloat16* aH = Asm + (buf * 2 + 0) * A_COPY;
        const __nv_bfloat16* aL = Asm + (buf * 2 + 1) * A_COPY;
        wmma::load_matrix_sync(ah0, aH + (m0 +  0) * ALD, ALD);
        wmma::load_matrix_sync(ah1, aH + (m0 + 16) * ALD, ALD);
        wmma::load_matrix_sync(al0, aL + (m0 +  0) * ALD, ALD);
        wmma::load_matrix_sync(al1, aL + (m0 + 16) * ALD, ALD);

        if (NT) {
            wmma::fragment<wmma::matrix_b, 16, 16, 16, __nv_bfloat16,
                           wmma::col_major> bh0, bh1, bl0, bl1;
            const __nv_bfloat16* bH = Bsm + (buf * 2 + 0) * B_COPY;
            const __nv_bfloat16* bL = Bsm + (buf * 2 + 1) * B_COPY;
            wmma::load_matrix_sync(bh0, bH + (n0 +  0) * BLDNT, BLDNT);
            wmma::load_matrix_sync(bh1, bH + (n0 + 16) * BLDNT, BLDNT);
            wmma::load_matrix_sync(bl0, bL + (n0 +  0) * BLDNT, BLDNT);
            wmma::load_matrix_sync(bl1, bL + (n0 + 16) * BLDNT, BLDNT);
            wmma::mma_sync(acc[0][0], ah0, bh0, acc[0][0]);
            wmma::mma_sync(acc[0][1], ah0, bh1, acc[0][1]);
            wmma::mma_sync(acc[1][0], ah1, bh0, acc[1][0]);
            wmma::mma_sync(acc[1][1], ah1, bh1, acc[1][1]);
            wmma::mma_sync(acc[0][0], ah0, bl0, acc[0][0]);
            wmma::mma_sync(acc[0][1], ah0, bl1, acc[0][1]);
            wmma::mma_sync(acc[1][0], ah1, bl0, acc[1][0]);
            wmma::mma_sync(acc[1][1], ah1, bl1, acc[1][1]);
            wmma::mma_sync(acc[0][0], al0, bh0, acc[0][0]);
            wmma::mma_sync(acc[0][1], al0, bh1, acc[0][1]);
            wmma::mma_sync(acc[1][0], al1, bh0, acc[1][0]);
            wmma::mma_sync(acc[1][1], al1, bh1, acc[1][1]);
        } else {
            wmma::fragment<wmma::matrix_b, 16, 16, 16, __nv_bfloat16,
                           wmma::row_major> bh0, bh1, bl0, bl1;
            const __nv_bfloat16* bH = Bsm + (buf * 2 + 0) * B_COPY;
            const __nv_bfloat16* bL = Bsm + (buf * 2 + 1) * B_COPY;
            wmma::load_matrix_sync(bh0, bH + n0, BLDNN);
            wmma::load_matrix_sync(bh1, bH + n0 + 16, BLDNN);
            wmma::load_matrix_sync(bl0, bL + n0, BLDNN);
            wmma::load_matrix_sync(bl1, bL + n0 + 16, BLDNN);
            wmma::mma_sync(acc[0][0], ah0, bh0, acc[0][0]);
            wmma::mma_sync(acc[0][1], ah0, bh1, acc[0][1]);
            wmma::mma_sync(acc[1][0], ah1, bh0, acc[1][0]);
            wmma::mma_sync(acc[1][1], ah1, bh1, acc[1][1]);
            wmma::mma_sync(acc[0][0], ah0, bl0, acc[0][0]);
            wmma::mma_sync(acc[0][1], ah0, bl1, acc[0][1]);
            wmma::mma_sync(acc[1][0], ah1, bl0, acc[1][0]);
            wmma::mma_sync(acc[1][1], ah1, bl1, acc[1][1]);
            wmma::mma_sync(acc[0][0], al0, bh0, acc[0][0]);
            wmma::mma_sync(acc[0][1], al0, bh1, acc[0][1]);
            wmma::mma_sync(acc[1][0], al1, bh0, acc[1][0]);
            wmma::mma_sync(acc[1][1], al1, bh1, acc[1][1]);
        }
        if (k0 + 1 < nk) commit(buf ^ 1);
        __syncthreads();
    }

    // epilogue: stage each 16x16 frag, TWO float4s per lane (full coverage)
    float* st = &stage[warp * 256];
    int rr = lane >> 1, cc = (lane & 1) << 3;
    #pragma unroll
    for (int i = 0; i < 2; i++)
        #pragma unroll
        for (int j = 0; j < 2; j++) {
            wmma::store_matrix_sync(st, acc[i][j], 16, wmma::mem_row_major);
            __syncwarp();
            int gr = row0 + m0 + 16 * i + rr;
            int gc = col0 + n0 + 16 * j + cc;
            float4 v0 = *(float4*)&st[rr * 16 + cc];
            float4 v1 = *(float4*)&st[rr * 16 + cc + 4];
            if (bias) {
                const float* bp = bias + gc;
                v0.x += bp[0]; v0.y += bp[1]; v0.z += bp[2]; v0.w += bp[3];
                v1.x += bp[4]; v1.y += bp[5]; v1.z += bp[6]; v1.w += bp[7];
            }
            *(float4*)(C + (size_t)gr * ldc + gc) = v0;
            *(float4*)(C + (size_t)gr * ldc + gc + 4) = v1;
            __syncwarp();
        }
}

// ---------------------------------------------------------------------------
// Rank-4 folds: init + ONE merged split-K kernel (z selects config).
// ---------------------------------------------------------------------------
__global__ void fold_init(float* __restrict__ Mv, float* __restrict__ cv,
                          const float* __restrict__ bv,
                          float* __restrict__ Rk, float* __restrict__ s1,
                          const float* __restrict__ bk,
                          float* __restrict__ Rq, float* __restrict__ sq,
                          const float* __restrict__ bq,
                          float* __restrict__ Mc, float* __restrict__ cc,
                          const float* __restrict__ pb) {
    int i = blockIdx.x * blockDim.x + threadIdx.x;
    if (i < 4 * DM) {
        Mv[i] = 0.f; Rk[i] = 0.f; Rq[i] = 0.f;
        if (i < 4 * Ee) Mc[i] = 0.f;
    } else {
        int j = i - 4 * DM;
        if (j < DM) {
            cv[j] = bv[j]; s1[j] = bk[j]; sq[j] = bq[j];
            if (j < Ee) cc[j] = pb[j];
        }
    }
}

#define FOLD_KSPLIT 16
__global__ void __launch_bounds__(128) fuse_all(
        const float* __restrict__ pos_W, const float* __restrict__ pos_b,
        const float* __restrict__ cand_W, const float* __restrict__ cand_b,
        const float* __restrict__ WvB, const float* __restrict__ WkB,
        const float* __restrict__ WqB, const float* __restrict__ projW,
        float* __restrict__ Mv, float* __restrict__ cv,
        float* __restrict__ Rk, float* __restrict__ s1,
        float* __restrict__ Rq, float* __restrict__ sq,
        float* __restrict__ Mc, float* __restrict__ cc) {
    int z = blockIdx.z;
    const float* W4   = (z == 3) ? cand_W : pos_W;
    const float* b_in = (z == 3) ? cand_b : pos_b;
    const float* Wbot = (z == 0) ? WvB : (z == 1) ? WkB : (z == 2) ? WqB : projW;
    float* M_out = (z == 0) ? Mv : (z == 1) ? Rk : (z == 2) ? Rq : Mc;
    float* c_out = (z == 0) ? cv : (z == 1) ? s1 : (z == 2) ? sq : cc;
    int Nout = (z == 3) ? Ee : DM;
    int ldb  = Nout;

    int n = blockIdx.x * 128 + threadIdx.x;
    if (n >= Nout) return;
    const int chunk = Ee / FOLD_KSPLIT;     // 32
    int k0 = blockIdx.y * chunk, k1 = k0 + chunk;
    float m0 = 0.f, m1 = 0.f, m2 = 0.f, m3 = 0.f, c = 0.f;
    for (int k = k0; k < k1; k++) {
        float w = Wbot[(size_t)k * ldb + n];
        m0 += W4[k] * w;
        m1 += W4[Ee + k] * w;
        m2 += W4[2 * Ee + k] * w;
        m3 += W4[3 * Ee + k] * w;
        c  += b_in[k] * w;
    }
    atomicAdd(&M_out[n], m0);
    atomicAdd(&M_out[Nout + n], m1);
    atomicAdd(&M_out[2 * Nout + n], m2);
    atomicAdd(&M_out[3 * Nout + n], m3);
    atomicAdd(&c_out[n], c);
}

// ---------------------------------------------------------------------------
__global__ void build_tq(const int* __restrict__ nt, const float* __restrict__ text_table,
                         float* __restrict__ Tq) {
    int r = blockIdx.x;
    int b = r >> 1, i = r & 1;
    int id = nt[b * Nn + i];
    const float4* src = (const float4*)(text_table + (size_t)id * Ee);
    float4* dst = (float4*)(Tq + (size_t)r * Ee);
    dst[threadIdx.x] = src[threadIdx.x];
}

// ---------------------------------------------------------------------------
__global__ void q_post(float* __restrict__ Q, const int* dummy,
                       const float* __restrict__ npos,
                       const float* __restrict__ Rq, const float* __restrict__ sq) {
    int idx = blockIdx.x * blockDim.x + threadIdx.x;
    if (idx >= 2 * Bsz * DM / 4) return;
    int r = idx >> 8;
    int c4 = (idx & 255) * 4;
    int b = r >> 1, i = r & 1;
    float4 p = *(const float4*)(npos + (size_t)(b * Nn + i) * 4);
    float4 v = *(float4*)(Q + (size_t)r * DM + c4);
    #pragma unroll
    for (int u = 0; u < 4; u++) {
        int c = c4 + u;
        (&v.x)[u] += sq[c] + p.x * Rq[c] + p.y * Rq[DM + c]
                   + p.z * Rq[2 * DM + c] + p.w * Rq[3 * DM + c];
    }
    *(float4*)(Q + (size_t)r * DM + c4) = v;
}

// ---------------------------------------------------------------------------
__global__ void __launch_bounds__(256) score_consts2(
        const float* __restrict__ Q, const float* __restrict__ Rk,
        const float* __restrict__ s1, float* __restrict__ r4, float* __restrict__ c0) {
    int warp = threadIdx.x >> 5, lane = threadIdx.x & 31;
    int i = blockIdx.x * 8 + warp;
    int bq = i >> 3, h = i & 7;
    float4 qv = *(const float4*)(Q + (size_t)bq * DM + h * DEPTH + lane * 4);
    #pragma unroll
    for (int c = 0; c < 5; c++) {
        const float* src = (c < 4) ? (Rk + c * DM) : s1;
        float4 rv = *(const float4*)(src + h * DEPTH + lane * 4);
        float s = qv.x * rv.x + qv.y * rv.y + qv.z * rv.z + qv.w * rv.w;
        #pragma unroll
        for (int off = 16; off; off >>= 1) s += __shfl_xor_sync(0xffffffffu, s, off);
        if (lane == 0) {
            if (c < 4) r4[i * 4 + c] = s;
            else       c0[i] = s;
        }
    }
}

// ---------------------------------------------------------------------------
// Fused attention: scores (gather-dot) -> softmax -> xbar (gather-axpy).
// ---------------------------------------------------------------------------
#define ATTN_SMEM (13736 * 4)

__global__ void __launch_bounds__(256) attn_fused(
        const int* __restrict__ nt, const float* __restrict__ npos,
        const float* __restrict__ U, const float* __restrict__ r4,
        const float* __restrict__ c0, const float* __restrict__ text_table,
        float* __restrict__ xbar, float* __restrict__ wpos) {
    extern __shared__ float dyn[];
    float* sUt  = dyn;                  // [512][16]
    float* sT   = dyn + 8192;           // [100][33]
    float* sS   = dyn + 11492;          // [16][104]
    float* spos = dyn + 13156;          // [100][4]
    float* sr4  = dyn + 13556;          // [16][4]
    float* sc0  = dyn + 13620;          // [16]
    int*   sid  = (int*)(dyn + 13636);  // [100]

    int b = blockIdx.x, tid = threadIdx.x;
    int warp = tid >> 5, lane = tid & 31;

    for (int n = tid; n < Nn; n += 256) {
        int id = nt[b * Nn + n];
        sid[n] = id;
        float4 p = *(const float4*)(npos + (size_t)(b * Nn + n) * 4);
        spos[n * 4 + 0] = p.x; spos[n * 4 + 1] = p.y;
        spos[n * 4 + 2] = p.z; spos[n * 4 + 3] = p.w;
    }
    for (int idx = tid; idx < 16 * Ee; idx += 256) {
        int qh = idx >> 9, d = idx & 511;
        sUt[d * 16 + qh] = U[((size_t)b * 16 + qh) * Ee + d];
    }
    for (int idx = tid; idx < 64; idx += 256) sr4[idx] = r4[(size_t)b * 64 + idx];
    if (tid < 16) sc0[tid] = c0[(size_t)b * 16 + tid];
    __syncthreads();

    float m0 = (sid[0] == 0) ? 1.f : 0.f;
    float m1 = (sid[1] == 0) ? 1.f : 0.f;
    const float scale = 0.08838834764831845f;

    bool active = tid < 200;
    int qh0 = (tid & 7) * 2;
    int n0 = (tid >> 3) * 4;
    float acc[2][4] = {};

    for (int kc = 0; kc < 16; kc++) {
        for (int idx = tid; idx < Nn * 32; idx += 256) {
            int n = idx >> 5, d = idx & 31;
            sT[n * 33 + d] = text_table[(size_t)sid[n] * Ee + kc * 32 + d];
        }
        __syncthreads();
        if (active) {
            #pragma unroll
            for (int d = 0; d < 32; d++) {
                int gd = kc * 32 + d;
                float2 u2 = *(float2*)&sUt[gd * 16 + qh0];
                #pragma unroll
                for (int i = 0; i < 4; i++) {
                    float t = sT[(n0 + i) * 33 + d];
                    acc[0][i] += u2.x * t;
                    acc[1][i] += u2.y * t;
                }
            }
        }
        __syncthreads();
    }
    if (active) {
        #pragma unroll
        for (int j = 0; j < 2; j++) {
            int qh = qh0 + j;
            float mq = (qh < 8) ? m0 : m1;
            #pragma unroll
            for (int i = 0; i < 4; i++) {
                int n = n0 + i;
                float s = acc[j][i]
                        + spos[n * 4 + 0] * sr4[qh * 4 + 0]
                        + spos[n * 4 + 1] * sr4[qh * 4 + 1]
                        + spos[n * 4 + 2] * sr4[qh * 4 + 2]
                        + spos[n * 4 + 3] * sr4[qh * 4 + 3]
                        + sc0[qh];
                float mn = (sid[n] == 0) ? 1.f : 0.f;
                sS[qh * 104 + n] = s * scale + mq * mn * (-1e9f);
            }
        }
    }
    __syncthreads();

    for (int r = warp; r < 16; r += 8) {
        float* row = sS + r * 104;
        float mx = -1e30f;
        for (int jn = lane; jn < Nn; jn += 32) mx = fmaxf(mx, row[jn]);
        #pragma unroll
        for (int off = 16; off; off >>= 1)
            mx = fmaxf(mx, __shfl_xor_sync(0xffffffffu, mx, off));
        float ev[4]; int cnt = 0; float sum = 0.f;
        for (int jn = lane; jn < Nn; jn += 32) {
            float e = expf(row[jn] - mx);
            ev[cnt++] = e; sum += e;
        }
        #pragma unroll
        for (int off = 16; off; off >>= 1)
            sum += __shfl_xor_sync(0xffffffffu, sum, off);
        float inv = 1.f / sum;
        cnt = 0;
        for (int jn = lane; jn < Nn; jn += 32) row[jn] = ev[cnt++] * inv;
    }
    __syncthreads();

    if (tid < 64) {
        int qh = tid >> 2, c = tid & 3;
        float s = 0.f;
        for (int n = 0; n < Nn; n++) s += sS[qh * 104 + n] * spos[n * 4 + c];
        wpos[((size_t)b * 16 + qh) * 4 + c] = s;
    }

    float* sT2 = dyn;
    int qh = tid & 15, dg = tid >> 4;
    float xa[32] = {};
    for (int nc = 0; nc < 7; nc++) {
        __syncthreads();
        for (int idx = tid; idx < 16 * Ee; idx += 256) {
            int rr = idx >> 9, d = idx & 511;
            int n = nc * 16 + rr;
            if (n < Nn) sT2[rr * Ee + d] = text_table[(size_t)sid[n] * Ee + d];
        }
        __syncthreads();
        int nmax = min(16, Nn - nc * 16);
        for (int rr = 0; rr < nmax; rr++) {
            float w = sS[qh * 104 + nc * 16 + rr];
            const float* tp = sT2 + rr * Ee + dg;
            #pragma unroll
            for (int j = 0; j < 32; j++) xa[j] += w * tp[16 * j];
        }
    }
    __syncthreads();
    float* sX = dyn;
    #pragma unroll
    for (int j = 0; j < 32; j++) sX[qh * Ee + dg + 16 * j] = xa[j];
    __syncthreads();
    for (int idx = tid; idx < 16 * Ee; idx += 256) {
        int q2 = idx >> 9, d = idx & 511;
        xbar[((size_t)b * 16 + q2) * Ee + d] = sX[idx];
    }
}

// ---------------------------------------------------------------------------
__global__ void att_post(float* __restrict__ att, const float* __restrict__ wpos,
                         const float* __restrict__ Mv, const float* __restrict__ cv) {
    int idx = blockIdx.x * blockDim.x + threadIdx.x;
    if (idx >= 2 * Bsz * DM / 4) return;
    int r = idx >> 8;
    int c4 = (idx & 255) * 4;
    int z = c4 >> 7;
    const float* wp = wpos + ((size_t)r * 8 + z) * 4;
    float w0 = wp[0], w1 = wp[1], w2 = wp[2], w3 = wp[3];
    float4 v = *(float4*)(att + (size_t)r * DM + c4);
    #pragma unroll
    for (int u = 0; u < 4; u++) {
        int c = c4 + u;
        (&v.x)[u] += cv[c] + w0 * Mv[c] + w1 * Mv[DM + c]
                   + w2 * Mv[2 * DM + c] + w3 * Mv[3 * DM + c];
    }
    *(float4*)(att + (size_t)r * DM + c4) = v;
}

// ---------------------------------------------------------------------------
__global__ void __launch_bounds__(128) cosine_kernel(
        const float* __restrict__ enc, const float* __restrict__ cand_pos,
        const float* __restrict__ Mc, const int* __restrict__ field_id,
        const float* __restrict__ field_table, float* __restrict__ out) {
    __shared__ float red[3][4];
    int b = blockIdx.x, t = threadIdx.x;
    int warp = t >> 5, lane = t & 31;
    const float* fp = field_table + (size_t)field_id[b] * Ee;
    float4 cp = *(const float4*)(cand_pos + (size_t)b * 4);
    float na = 0.f, nb = 0.f, dp = 0.f;
    for (int j = t; j < Ee; j += 128) {
        float e = enc[(size_t)b * Ee + j]
                + cp.x * Mc[j] + cp.y * Mc[Ee + j]
                + cp.z * Mc[2 * Ee + j] + cp.w * Mc[3 * Ee + j];
        float f = fp[j];
        na += e * e; nb += f * f; dp += e * f;
    }
    #pragma unroll
    for (int off = 16; off; off >>= 1) {
        na += __shfl_xor_sync(0xffffffffu, na, off);
        nb += __shfl_xor_sync(0xffffffffu, nb, off);
        dp += __shfl_xor_sync(0xffffffffu, dp, off);
    }
    if (lane == 0) { red[0][warp] = na; red[1][warp] = nb; red[2][warp] = dp; }
    __syncthreads();
    if (t == 0) {
        na = red[0][0] + red[0][1] + red[0][2] + red[0][3];
        nb = red[1][0] + red[1][1] + red[1][2] + red[1][3];
        dp = red[2][0] + red[2][1] + red[2][2] + red[2][3];
        out[b] = -dp * rsqrtf(fmaxf(na, 1e-12f)) * rsqrtf(fmaxf(nb, 1e-12f));
    }
}

// ---------------------------------------------------------------------------
extern "C" void kernel_launch(void* const* d_in, const int* in_sizes, int n_in,
                              void* d_out, int out_size) {
    const int*   field_id   = (const int*)  d_in[0];
    const float* cand_pos   = (const float*)d_in[1];
    const int*   nt         = (const int*)  d_in[2];
    const float* npos       = (const float*)d_in[3];
    const float* text_table = (const float*)d_in[4];
    const float* field_tab  = (const float*)d_in[5];
    const float* cand_W     = (const float*)d_in[6];
    const float* cand_b     = (const float*)d_in[7];
    const float* pos_W      = (const float*)d_in[8];
    const float* pos_b      = (const float*)d_in[9];
    const float* Wq         = (const float*)d_in[10];
    const float* bq         = (const float*)d_in[11];
    const float* Wk         = (const float*)d_in[12];
    const float* bk         = (const float*)d_in[13];
    const float* Wv         = (const float*)d_in[14];
    const float* bv         = (const float*)d_in[15];
    const float* Wo         = (const float*)d_in[16];
    const float* bo         = (const float*)d_in[17];
    const float* proj_W     = (const float*)d_in[18];
    const float* proj_b     = (const float*)d_in[19];
    float* out = (float*)d_out;

    float *Tq, *Qb, *Ub, *r4b, *c0b, *xbarb, *wposb, *attb, *Ob, *encb;
    float *Mvp, *cvp, *Mcp, *ccp, *Rkp, *s1p, *Rqp, *sqp;
    cudaGetSymbolAddress((void**)&Tq,    g_Tq);
    cudaGetSymbolAddress((void**)&Qb,    g_Q);
    cudaGetSymbolAddress((void**)&Ub,    g_U);
    cudaGetSymbolAddress((void**)&r4b,   g_r4);
    cudaGetSymbolAddress((void**)&c0b,   g_c0);
    cudaGetSymbolAddress((void**)&xbarb, g_xbar);
    cudaGetSymbolAddress((void**)&wposb, g_wpos);
    cudaGetSymbolAddress((void**)&attb,  g_att);
    cudaGetSymbolAddress((void**)&Ob,    g_O);
    cudaGetSymbolAddress((void**)&encb,  g_enc);
    cudaGetSymbolAddress((void**)&Mvp,   g_Mv);
    cudaGetSymbolAddress((void**)&cvp,   g_cv);
    cudaGetSymbolAddress((void**)&Mcp,   g_Mc);
    cudaGetSymbolAddress((void**)&ccp,   g_cc);
    cudaGetSymbolAddress((void**)&Rkp,   g_Rk);
    cudaGetSymbolAddress((void**)&s1p,   g_s1);
    cudaGetSymbolAddress((void**)&Rqp,   g_Rq);
    cudaGetSymbolAddress((void**)&sqp,   g_sq);

    cudaFuncSetAttribute(attn_fused,
                         cudaFuncAttributeMaxDynamicSharedMemorySize, ATTN_SMEM);
    cudaFuncSetAttribute(wmma_gemm3<false, false>,
                         cudaFuncAttributeMaxDynamicSharedMemorySize, GSMEM_BYTES);
    cudaFuncSetAttribute(wmma_gemm3<true, false>,
                         cudaFuncAttributeMaxDynamicSharedMemorySize, GSMEM_BYTES);
    cudaFuncSetAttribute(wmma_gemm3<false, true>,
                         cudaFuncAttributeMaxDynamicSharedMemorySize, GSMEM_BYTES);

    // ---- rank-4 folds: init + ONE merged split-K launch ----
    fold_init<<<(5 * DM + 255) / 256, 256>>>(Mvp, cvp, bv, Rkp, s1p, bk,
                                             Rqp, sqp, bq, Mcp, ccp, proj_b);
    fuse_all<<<dim3(DM / 128, FOLD_KSPLIT, 4), 128>>>(
        pos_W, pos_b, cand_W, cand_b,
        Wv + (size_t)Ee * DM, Wk + (size_t)Ee * DM, Wq + (size_t)Ee * DM, proj_W,
        Mvp, cvp, Rkp, s1p, Rqp, sqp, Mcp, ccp);

    // gather text rows for q positions
    build_tq<<<2 * Bsz, 128>>>(nt, text_table, Tq);

    // Q = Tq @ Wq_top  (1024 x 1024 x 512) + rank-4 epilogue
    wmma_gemm3<false, false><<<dim3(8, 16, 1), 256, GSMEM_BYTES>>>(
        Tq, Ee, 0, Wq, DM, 0, Qb, DM, 0, nullptr, Ee);
    q_post<<<(2 * Bsz * DM / 4 + 255) / 256, 256>>>(Qb, nullptr, npos, Rqp, sqp);

    // U_top = q_h @ Wk_top_h^T  (8 x [1024 x 512 x 128] NT)
    wmma_gemm3<true, false><<<dim3(4, 16, 8), 256, GSMEM_BYTES>>>(
        Qb, DM, 128, Wk, DM, 128, Ub, 8 * Ee, Ee, nullptr, DEPTH);

    // per-(bq,h) score constants
    score_consts2<<<16 * Bsz / 8, 256>>>(Qb, Rkp, s1p, r4b, c0b);

    // fused gather-scores -> softmax -> xbar/wpos
    attn_fused<<<Bsz, 256, ATTN_SMEM>>>(nt, npos, Ub, r4b, c0b, text_table,
                                        xbarb, wposb);

    // att = xbar @ Wv_top  (8 x [1024 x 128 x 512])
    wmma_gemm3<false, false><<<dim3(1, 16, 8), 256, GSMEM_BYTES>>>(
        xbarb, 8 * Ee, Ee, Wv, DM, 128, attb, DM, 128, nullptr, Ee);
    att_post<<<(2 * Bsz * DM / 4 + 255) / 256, 256>>>(attb, wposb, Mvp, cvp);

    // O = att @ Wo + bo  (1024 x 1024 x 1024)
    wmma_gemm3<false, false><<<dim3(8, 16, 1), 256, GSMEM_BYTES>>>(
        attb, DM, 0, Wo, DM, 0, Ob, DM, 0, bo, DM);

    // enc = max-pool(O rows) @ proj_W[512:,:] + cc  (pool fused)
    wmma_gemm3<false, true><<<dim3(4, 8, 1), 256, GSMEM_BYTES>>>(
        Ob, DM, 0, proj_W + (size_t)Ee * Ee, Ee, 0, encb, Ee, 0, ccp, DM);

    // cosine loss
    cosine_kernel<<<Bsz, 128>>>(encb, cand_pos, Mcp, field_id, field_tab, out);
}

// round 15
// speedup vs baseline: 4.3348x; 1.1273x over previous
#include <cuda_runtime.h>
#include <cuda_bf16.h>
#include <mma.h>
#include <cstdint>

using namespace nvcuda;

// ---------------------------------------------------------------------------
// Model_57183194578962 — fused neighbor-attention + cosine loss
// B=512, N=100, E=512, D_MODEL=1024, H=8, DEPTH=128, VOCAB=50000
//
// Round 14: engine v4 — K-chunk 32 (24 MMAs/sync, half the syncs),
// GATHER flag folds the text-table row gather into the Q GEMM A-fetch.
// ---------------------------------------------------------------------------

#define Bsz 512
#define Nn  100
#define Ee  512
#define DM  1024
#define Hh  8
#define DEPTH 128

// ------------------------- static scratch ----------------------------------
__device__ float g_Q [2 * Bsz * DM];
__device__ float g_U [16 * Bsz * Ee];
__device__ float g_r4[16 * Bsz * 4];
__device__ float g_c0[16 * Bsz];
__device__ float g_xbar[16 * Bsz * Ee];
__device__ float g_wpos[16 * Bsz * 4];
__device__ float g_att[2 * Bsz * DM];
__device__ float g_O [2 * Bsz * DM];
__device__ float g_enc[Bsz * Ee];
__device__ float g_Mv[4 * DM], g_cv[DM];
__device__ float g_Mc[4 * Ee], g_cc[Ee];
__device__ float g_Rk[4 * DM], g_s1[DM];
__device__ float g_Rq[4 * DM], g_sq[DM];

// ---------------------------------------------------------------------------
// WMMA bf16 split GEMM engine v4.
//   C = A @ B (+bias). CTA 64(M) x 128(N), K-chunk 32 (2 x k16 sub-steps),
//   double buffered; hi/lo bf16 resident; 3 passes (hh+hl+lh) ~= fp32.
//   NT: B[n][k] row-major source. POOL: A row m = max(Asrc[2m], Asrc[2m+1]).
//   GATHER: A row r sourced from text_table[nt[(r>>1)*Nn + (r&1)]].
// smem (bytes): Asm 4x2560 bf16 [0,20480) ; Bsm 4x5120 bf16 [20480,61440) ;
//               stage 8x256 fp32 [61440,69632)
// ---------------------------------------------------------------------------
#define ALD 40
#define BLDNN 136
#define BLDNT 40
#define A_COPY 2560
#define B_COPY 5120
#define GSMEM_BYTES 69632

template<bool NT, bool POOL, bool GATHER>
__global__ void __launch_bounds__(256) wmma_gemm4(
        const float* __restrict__ A0, int lda, long az,
        const float* __restrict__ B0, int ldb, long bz,
        float* __restrict__ C0, int ldc, long cz,
        const float* __restrict__ bias, int K,
        const int* __restrict__ nt) {
    const float* A = A0 + (size_t)blockIdx.z * az;
    const float* B = B0 + (size_t)blockIdx.z * bz;
    float*       C = C0 + (size_t)blockIdx.z * cz;

    extern __shared__ char smraw[];
    __nv_bfloat16* Asm = (__nv_bfloat16*)smraw;
    __nv_bfloat16* Bsm = (__nv_bfloat16*)(smraw + 20480);
    float* stage = (float*)(smraw + 61440);

    int tid = threadIdx.x;
    int warp = tid >> 5, lane = tid & 31;
    int row0 = blockIdx.y * 64, col0 = blockIdx.x * 128;
    int wm = warp >> 2, wn = warp & 3;
    int m0 = wm * 32, n0 = wn * 32;

    // A load mapping: 4 threads/row, 8 k-values each (2 float4)
    int arr = tid >> 2, ak8 = (tid & 3) << 3;
    // B NN: 8 threads/row over 32 rows, 16 cols each (4 float4)
    int bkr = tid >> 3, bc = (tid & 7) << 4;
    // B NT: 2 threads/n-row over 128 rows, 16 k each (4 float4)
    int bi = tid >> 1, bko = (tid & 1) << 4;

    // resolve A row pointers once (gather / pool / plain)
    const float *Ar0, *Ar1 = nullptr;
    if (GATHER) {
        int gr = row0 + arr;
        int id = nt[(gr >> 1) * Nn + (gr & 1)];
        Ar0 = A + (size_t)id * lda;
    } else if (POOL) {
        Ar0 = A + (size_t)(2 * (row0 + arr)) * lda;
        Ar1 = A + (size_t)(2 * (row0 + arr) + 1) * lda;
    } else {
        Ar0 = A + (size_t)(row0 + arr) * lda;
    }

    const int nk = K >> 5;

    float4 fa0, fa1, fb[4];
    auto fetch = [&](int c) {
        int kb = c << 5;
        fa0 = *(const float4*)(Ar0 + kb + ak8);
        fa1 = *(const float4*)(Ar0 + kb + ak8 + 4);
        if (POOL) {
            float4 y0 = *(const float4*)(Ar1 + kb + ak8);
            float4 y1 = *(const float4*)(Ar1 + kb + ak8 + 4);
            fa0.x = fmaxf(fa0.x, y0.x); fa0.y = fmaxf(fa0.y, y0.y);
            fa0.z = fmaxf(fa0.z, y0.z); fa0.w = fmaxf(fa0.w, y0.w);
            fa1.x = fmaxf(fa1.x, y1.x); fa1.y = fmaxf(fa1.y, y1.y);
            fa1.z = fmaxf(fa1.z, y1.z); fa1.w = fmaxf(fa1.w, y1.w);
        }
        if (NT) {
            const float* bp = B + (size_t)(col0 + bi) * ldb + kb + bko;
            #pragma unroll
            for (int q = 0; q < 4; q++) fb[q] = *(const float4*)(bp + 4 * q);
        } else {
            const float* bp = B + (size_t)(kb + bkr) * ldb + col0 + bc;
            #pragma unroll
            for (int q = 0; q < 4; q++) fb[q] = *(const float4*)(bp + 4 * q);
        }
    };
    auto commit = [&](int buf) {
        __nv_bfloat16* ah = Asm + (buf * 2 + 0) * A_COPY + arr * ALD + ak8;
        __nv_bfloat16* al = Asm + (buf * 2 + 1) * A_COPY + arr * ALD + ak8;
        #pragma unroll
        for (int u = 0; u < 4; u++) {
            float x = (&fa0.x)[u];
            __nv_bfloat16 h = __float2bfloat16(x);
            ah[u] = h; al[u] = __float2bfloat16(x - __bfloat162float(h));
            float y = (&fa1.x)[u];
            __nv_bfloat16 g = __float2bfloat16(y);
            ah[4 + u] = g; al[4 + u] = __float2bfloat16(y - __bfloat162float(g));
        }
        __nv_bfloat16 *bh, *bl;
        if (NT) {
            bh = Bsm + (buf * 2 + 0) * B_COPY + bi * BLDNT + bko;
            bl = Bsm + (buf * 2 + 1) * B_COPY + bi * BLDNT + bko;
        } else {
            bh = Bsm + (buf * 2 + 0) * B_COPY + bkr * BLDNN + bc;
            bl = Bsm + (buf * 2 + 1) * B_COPY + bkr * BLDNN + bc;
        }
        #pragma unroll
        for (int q = 0; q < 4; q++)
            #pragma unroll
            for (int u = 0; u < 4; u++) {
                float x = (&fb[q].x)[u];
                __nv_bfloat16 h = __float2bfloat16(x);
                bh[4 * q + u] = h;
                bl[4 * q + u] = __float2bfloat16(x - __bfloat162float(h));
            }
    };

    fetch(0);
    commit(0);
    __syncthreads();

    wmma::fragment<wmma::accumulator, 16, 16, 16, float> acc[2][2];
    #pragma unroll
    for (int i = 0; i < 2; i++)
        #pragma unroll
        for (int j = 0; j < 2; j++)
            wmma::fill_fragment(acc[i][j], 0.0f);

    for (int k0 = 0; k0 < nk; k0++) {
        int buf = k0 & 1;
        if (k0 + 1 < nk) fetch(k0 + 1);

        const __nv_bfloat16* aH = Asm + (buf * 2 + 0) * A_COPY;
        const __nv_bfloat16* aL = Asm + (buf * 2 + 1) * A_COPY;
        const __nv_bfloat16* bH = Bsm + (buf * 2 + 0) * B_COPY;
        const __nv_bfloat16* bL = Bsm + (buf * 2 + 1) * B_COPY;

        #pragma unroll
        for (int k2 = 0; k2 < 2; k2++) {
            int ko = k2 << 4;
            wmma::fragment<wmma::matrix_a, 16, 16, 16, __nv_bfloat16,
                           wmma::row_major> ah0, ah1, al0, al1;
            wmma::load_matrix_sync(ah0, aH + (m0 +  0) * ALD + ko, ALD);
            wmma::load_matrix_sync(ah1, aH + (m0 + 16) * ALD + ko, ALD);
            wmma::load_matrix_sync(al0, aL + (m0 +  0) * ALD + ko, ALD);
            wmma::load_matrix_sync(al1, aL + (m0 + 16) * ALD + ko, ALD);
            if (NT) {
                wmma::fragment<wmma::matrix_b, 16, 16, 16, __nv_bfloat16,
                               wmma::col_major> bh0, bh1, bl0, bl1;
                wmma::load_matrix_sync(bh0, bH + (n0 +  0) * BLDNT + ko, BLDNT);
                wmma::load_matrix_sync(bh1, bH + (n0 + 16) * BLDNT + ko, BLDNT);
                wmma::load_matrix_sync(bl0, bL + (n0 +  0) * BLDNT + ko, BLDNT);
                wmma::load_matrix_sync(bl1, bL + (n0 + 16) * BLDNT + ko, BLDNT);
                wmma::mma_sync(acc[0][0], ah0, bh0, acc[0][0]);
                wmma::mma_sync(acc[0][1], ah0, bh1, acc[0][1]);
                wmma::mma_sync(acc[1][0], ah1, bh0, acc[1][0]);
                wmma::mma_sync(acc[1][1], ah1, bh1, acc[1][1]);
                wmma::mma_sync(acc[0][0], ah0, bl0, acc[0][0]);
                wmma::mma_sync(acc[0][1], ah0, bl1, acc[0][1]);
                wmma::mma_sync(acc[1][0], ah1, bl0, acc[1][0]);
                wmma::mma_sync(acc[1][1], ah1, bl1, acc[1][1]);
                wmma::mma_sync(acc[0][0], al0, bh0, acc[0][0]);
                wmma::mma_sync(acc[0][1], al0, bh1, acc[0][1]);
                wmma::mma_sync(acc[1][0], al1, bh0, acc[1][0]);
                wmma::mma_sync(acc[1][1], al1, bh1, acc[1][1]);
            } else {
                wmma::fragment<wmma::matrix_b, 16, 16, 16, __nv_bfloat16,
                               wmma::row_major> bh0, bh1, bl0, bl1;
                wmma::load_matrix_sync(bh0, bH + ko * BLDNN + n0, BLDNN);
                wmma::load_matrix_sync(bh1, bH + ko * BLDNN + n0 + 16, BLDNN);
                wmma::load_matrix_sync(bl0, bL + ko * BLDNN + n0, BLDNN);
                wmma::load_matrix_sync(bl1, bL + ko * BLDNN + n0 + 16, BLDNN);
                wmma::mma_sync(acc[0][0], ah0, bh0, acc[0][0]);
                wmma::mma_sync(acc[0][1], ah0, bh1, acc[0][1]);
                wmma::mma_sync(acc[1][0], ah1, bh0, acc[1][0]);
                wmma::mma_sync(acc[1][1], ah1, bh1, acc[1][1]);
                wmma::mma_sync(acc[0][0], ah0, bl0, acc[0][0]);
                wmma::mma_sync(acc[0][1], ah0, bl1, acc[0][1]);
                wmma::mma_sync(acc[1][0], ah1, bl0, acc[1][0]);
                wmma::mma_sync(acc[1][1], ah1, bl1, acc[1][1]);
                wmma::mma_sync(acc[0][0], al0, bh0, acc[0][0]);
                wmma::mma_sync(acc[0][1], al0, bh1, acc[0][1]);
                wmma::mma_sync(acc[1][0], al1, bh0, acc[1][0]);
                wmma::mma_sync(acc[1][1], al1, bh1, acc[1][1]);
            }
        }
        if (k0 + 1 < nk) commit(buf ^ 1);
        __syncthreads();
    }

    // epilogue: stage each 16x16 frag, TWO float4s per lane (full coverage)
    float* st = &stage[warp * 256];
    int rr = lane >> 1, cc = (lane & 1) << 3;
    #pragma unroll
    for (int i = 0; i < 2; i++)
        #pragma unroll
        for (int j = 0; j < 2; j++) {
            wmma::store_matrix_sync(st, acc[i][j], 16, wmma::mem_row_major);
            __syncwarp();
            int gr = row0 + m0 + 16 * i + rr;
            int gc = col0 + n0 + 16 * j + cc;
            float4 v0 = *(float4*)&st[rr * 16 + cc];
            float4 v1 = *(float4*)&st[rr * 16 + cc + 4];
            if (bias) {
                const float* bp = bias + gc;
                v0.x += bp[0]; v0.y += bp[1]; v0.z += bp[2]; v0.w += bp[3];
                v1.x += bp[4]; v1.y += bp[5]; v1.z += bp[6]; v1.w += bp[7];
            }
            *(float4*)(C + (size_t)gr * ldc + gc) = v0;
            *(float4*)(C + (size_t)gr * ldc + gc + 4) = v1;
            __syncwarp();
        }
}

// ---------------------------------------------------------------------------
// Rank-4 folds: init + ONE merged split-K kernel (z selects config).
// ---------------------------------------------------------------------------
__global__ void fold_init(float* __restrict__ Mv, float* __restrict__ cv,
                          const float* __restrict__ bv,
                          float* __restrict__ Rk, float* __restrict__ s1,
                          const float* __restrict__ bk,
                          float* __restrict__ Rq, float* __restrict__ sq,
                          const float* __restrict__ bq,
                          float* __restrict__ Mc, float* __restrict__ cc,
                          const float* __restrict__ pb) {
    int i = blockIdx.x * blockDim.x + threadIdx.x;
    if (i < 4 * DM) {
        Mv[i] = 0.f; Rk[i] = 0.f; Rq[i] = 0.f;
        if (i < 4 * Ee) Mc[i] = 0.f;
    } else {
        int j = i - 4 * DM;
        if (j < DM) {
            cv[j] = bv[j]; s1[j] = bk[j]; sq[j] = bq[j];
            if (j < Ee) cc[j] = pb[j];
        }
    }
}

#define FOLD_KSPLIT 16
__global__ void __launch_bounds__(128) fuse_all(
        const float* __restrict__ pos_W, const float* __restrict__ pos_b,
        const float* __restrict__ cand_W, const float* __restrict__ cand_b,
        const float* __restrict__ WvB, const float* __restrict__ WkB,
        const float* __restrict__ WqB, const float* __restrict__ projW,
        float* __restrict__ Mv, float* __restrict__ cv,
        float* __restrict__ Rk, float* __restrict__ s1,
        float* __restrict__ Rq, float* __restrict__ sq,
        float* __restrict__ Mc, float* __restrict__ cc) {
    int z = blockIdx.z;
    const float* W4   = (z == 3) ? cand_W : pos_W;
    const float* b_in = (z == 3) ? cand_b : pos_b;
    const float* Wbot = (z == 0) ? WvB : (z == 1) ? WkB : (z == 2) ? WqB : projW;
    float* M_out = (z == 0) ? Mv : (z == 1) ? Rk : (z == 2) ? Rq : Mc;
    float* c_out = (z == 0) ? cv : (z == 1) ? s1 : (z == 2) ? sq : cc;
    int Nout = (z == 3) ? Ee : DM;
    int ldb  = Nout;

    int n = blockIdx.x * 128 + threadIdx.x;
    if (n >= Nout) return;
    const int chunk = Ee / FOLD_KSPLIT;     // 32
    int k0 = blockIdx.y * chunk, k1 = k0 + chunk;
    float m0 = 0.f, m1 = 0.f, m2 = 0.f, m3 = 0.f, c = 0.f;
    for (int k = k0; k < k1; k++) {
        float w = Wbot[(size_t)k * ldb + n];
        m0 += W4[k] * w;
        m1 += W4[Ee + k] * w;
        m2 += W4[2 * Ee + k] * w;
        m3 += W4[3 * Ee + k] * w;
        c  += b_in[k] * w;
    }
    atomicAdd(&M_out[n], m0);
    atomicAdd(&M_out[Nout + n], m1);
    atomicAdd(&M_out[2 * Nout + n], m2);
    atomicAdd(&M_out[3 * Nout + n], m3);
    atomicAdd(&c_out[n], c);
}

// ---------------------------------------------------------------------------
__global__ void q_post(float* __restrict__ Q, const int* dummy,
                       const float* __restrict__ npos,
                       const float* __restrict__ Rq, const float* __restrict__ sq) {
    int idx = blockIdx.x * blockDim.x + threadIdx.x;
    if (idx >= 2 * Bsz * DM / 4) return;
    int r = idx >> 8;
    int c4 = (idx & 255) * 4;
    int b = r >> 1, i = r & 1;
    float4 p = *(const float4*)(npos + (size_t)(b * Nn + i) * 4);
    float4 v = *(float4*)(Q + (size_t)r * DM + c4);
    #pragma unroll
    for (int u = 0; u < 4; u++) {
        int c = c4 + u;
        (&v.x)[u] += sq[c] + p.x * Rq[c] + p.y * Rq[DM + c]
                   + p.z * Rq[2 * DM + c] + p.w * Rq[3 * DM + c];
    }
    *(float4*)(Q + (size_t)r * DM + c4) = v;
}

// ---------------------------------------------------------------------------
__global__ void __launch_bounds__(256) score_consts2(
        const float* __restrict__ Q, const float* __restrict__ Rk,
        const float* __restrict__ s1, float* __restrict__ r4, float* __restrict__ c0) {
    int warp = threadIdx.x >> 5, lane = threadIdx.x & 31;
    int i = blockIdx.x * 8 + warp;
    int bq = i >> 3, h = i & 7;
    float4 qv = *(const float4*)(Q + (size_t)bq * DM + h * DEPTH + lane * 4);
    #pragma unroll
    for (int c = 0; c < 5; c++) {
        const float* src = (c < 4) ? (Rk + c * DM) : s1;
        float4 rv = *(const float4*)(src + h * DEPTH + lane * 4);
        float s = qv.x * rv.x + qv.y * rv.y + qv.z * rv.z + qv.w * rv.w;
        #pragma unroll
        for (int off = 16; off; off >>= 1) s += __shfl_xor_sync(0xffffffffu, s, off);
        if (lane == 0) {
            if (c < 4) r4[i * 4 + c] = s;
            else       c0[i] = s;
        }
    }
}

// ---------------------------------------------------------------------------
// Fused attention: scores (gather-dot) -> softmax -> xbar (gather-axpy).
// ---------------------------------------------------------------------------
#define ATTN_SMEM (13736 * 4)

__global__ void __launch_bounds__(256) attn_fused(
        const int* __restrict__ nt, const float* __restrict__ npos,
        const float* __restrict__ U, const float* __restrict__ r4,
        const float* __restrict__ c0, const float* __restrict__ text_table,
        float* __restrict__ xbar, float* __restrict__ wpos) {
    extern __shared__ float dyn[];
    float* sUt  = dyn;                  // [512][16]
    float* sT   = dyn + 8192;           // [100][33]
    float* sS   = dyn + 11492;          // [16][104]
    float* spos = dyn + 13156;          // [100][4]
    float* sr4  = dyn + 13556;          // [16][4]
    float* sc0  = dyn + 13620;          // [16]
    int*   sid  = (int*)(dyn + 13636);  // [100]

    int b = blockIdx.x, tid = threadIdx.x;
    int warp = tid >> 5, lane = tid & 31;

    for (int n = tid; n < Nn; n += 256) {
        int id = nt[b * Nn + n];
        sid[n] = id;
        float4 p = *(const float4*)(npos + (size_t)(b * Nn + n) * 4);
        spos[n * 4 + 0] = p.x; spos[n * 4 + 1] = p.y;
        spos[n * 4 + 2] = p.z; spos[n * 4 + 3] = p.w;
    }
    for (int idx = tid; idx < 16 * Ee; idx += 256) {
        int qh = idx >> 9, d = idx & 511;
        sUt[d * 16 + qh] = U[((size_t)b * 16 + qh) * Ee + d];
    }
    for (int idx = tid; idx < 64; idx += 256) sr4[idx] = r4[(size_t)b * 64 + idx];
    if (tid < 16) sc0[tid] = c0[(size_t)b * 16 + tid];
    __syncthreads();

    float m0 = (sid[0] == 0) ? 1.f : 0.f;
    float m1 = (sid[1] == 0) ? 1.f : 0.f;
    const float scale = 0.08838834764831845f;

    bool active = tid < 200;
    int qh0 = (tid & 7) * 2;
    int n0 = (tid >> 3) * 4;
    float acc[2][4] = {};

    for (int kc = 0; kc < 16; kc++) {
        for (int idx = tid; idx < Nn * 32; idx += 256) {
            int n = idx >> 5, d = idx & 31;
            sT[n * 33 + d] = text_table[(size_t)sid[n] * Ee + kc * 32 + d];
        }
        __syncthreads();
        if (active) {
            #pragma unroll
            for (int d = 0; d < 32; d++) {
                int gd = kc * 32 + d;
                float2 u2 = *(float2*)&sUt[gd * 16 + qh0];
                #pragma unroll
                for (int i = 0; i < 4; i++) {
                    float t = sT[(n0 + i) * 33 + d];
                    acc[0][i] += u2.x * t;
                    acc[1][i] += u2.y * t;
                }
            }
        }
        __syncthreads();
    }
    if (active) {
        #pragma unroll
        for (int j = 0; j < 2; j++) {
            int qh = qh0 + j;
            float mq = (qh < 8) ? m0 : m1;
            #pragma unroll
            for (int i = 0; i < 4; i++) {
                int n = n0 + i;
                float s = acc[j][i]
                        + spos[n * 4 + 0] * sr4[qh * 4 + 0]
                        + spos[n * 4 + 1] * sr4[qh * 4 + 1]
                        + spos[n * 4 + 2] * sr4[qh * 4 + 2]
                        + spos[n * 4 + 3] * sr4[qh * 4 + 3]
                        + sc0[qh];
                float mn = (sid[n] == 0) ? 1.f : 0.f;
                sS[qh * 104 + n] = s * scale + mq * mn * (-1e9f);
            }
        }
    }
    __syncthreads();

    for (int r = warp; r < 16; r += 8) {
        float* row = sS + r * 104;
        float mx = -1e30f;
        for (int jn = lane; jn < Nn; jn += 32) mx = fmaxf(mx, row[jn]);
        #pragma unroll
        for (int off = 16; off; off >>= 1)
            mx = fmaxf(mx, __shfl_xor_sync(0xffffffffu, mx, off));
        float ev[4]; int cnt = 0; float sum = 0.f;
        for (int jn = lane; jn < Nn; jn += 32) {
            float e = expf(row[jn] - mx);
            ev[cnt++] = e; sum += e;
        }
        #pragma unroll
        for (int off = 16; off; off >>= 1)
            sum += __shfl_xor_sync(0xffffffffu, sum, off);
        float inv = 1.f / sum;
        cnt = 0;
        for (int jn = lane; jn < Nn; jn += 32) row[jn] = ev[cnt++] * inv;
    }
    __syncthreads();

    if (tid < 64) {
        int qh = tid >> 2, c = tid & 3;
        float s = 0.f;
        for (int n = 0; n < Nn; n++) s += sS[qh * 104 + n] * spos[n * 4 + c];
        wpos[((size_t)b * 16 + qh) * 4 + c] = s;
    }

    float* sT2 = dyn;
    int qh = tid & 15, dg = tid >> 4;
    float xa[32] = {};
    for (int nc = 0; nc < 7; nc++) {
        __syncthreads();
        for (int idx = tid; idx < 16 * Ee; idx += 256) {
            int rr = idx >> 9, d = idx & 511;
            int n = nc * 16 + rr;
            if (n < Nn) sT2[rr * Ee + d] = text_table[(size_t)sid[n] * Ee + d];
        }
        __syncthreads();
        int nmax = min(16, Nn - nc * 16);
        for (int rr = 0; rr < nmax; rr++) {
            float w = sS[qh * 104 + nc * 16 + rr];
            const float* tp = sT2 + rr * Ee + dg;
            #pragma unroll
            for (int j = 0; j < 32; j++) xa[j] += w * tp[16 * j];
        }
    }
    __syncthreads();
    float* sX = dyn;
    #pragma unroll
    for (int j = 0; j < 32; j++) sX[qh * Ee + dg + 16 * j] = xa[j];
    __syncthreads();
    for (int idx = tid; idx < 16 * Ee; idx += 256) {
        int q2 = idx >> 9, d = idx & 511;
        xbar[((size_t)b * 16 + q2) * Ee + d] = sX[idx];
    }
}

// ---------------------------------------------------------------------------
__global__ void att_post(float* __restrict__ att, const float* __restrict__ wpos,
                         const float* __restrict__ Mv, const float* __restrict__ cv) {
    int idx = blockIdx.x * blockDim.x + threadIdx.x;
    if (idx >= 2 * Bsz * DM / 4) return;
    int r = idx >> 8;
    int c4 = (idx & 255) * 4;
    int z = c4 >> 7;
    const float* wp = wpos + ((size_t)r * 8 + z) * 4;
    float w0 = wp[0], w1 = wp[1], w2 = wp[2], w3 = wp[3];
    float4 v = *(float4*)(att + (size_t)r * DM + c4);
    #pragma unroll
    for (int u = 0; u < 4; u++) {
        int c = c4 + u;
        (&v.x)[u] += cv[c] + w0 * Mv[c] + w1 * Mv[DM + c]
                   + w2 * Mv[2 * DM + c] + w3 * Mv[3 * DM + c];
    }
    *(float4*)(att + (size_t)r * DM + c4) = v;
}

// ---------------------------------------------------------------------------
__global__ void __launch_bounds__(128) cosine_kernel(
        const float* __restrict__ enc, const float* __restrict__ cand_pos,
        const float* __restrict__ Mc, const int* __restrict__ field_id,
        const float* __restrict__ field_table, float* __restrict__ out) {
    __shared__ float red[3][4];
    int b = blockIdx.x, t = threadIdx.x;
    int warp = t >> 5, lane = t & 31;
    const float* fp = field_table + (size_t)field_id[b] * Ee;
    float4 cp = *(const float4*)(cand_pos + (size_t)b * 4);
    float na = 0.f, nb = 0.f, dp = 0.f;
    for (int j = t; j < Ee; j += 128) {
        float e = enc[(size_t)b * Ee + j]
                + cp.x * Mc[j] + cp.y * Mc[Ee + j]
                + cp.z * Mc[2 * Ee + j] + cp.w * Mc[3 * Ee + j];
        float f = fp[j];
        na += e * e; nb += f * f; dp += e * f;
    }
    #pragma unroll
    for (int off = 16; off; off >>= 1) {
        na += __shfl_xor_sync(0xffffffffu, na, off);
        nb += __shfl_xor_sync(0xffffffffu, nb, off);
        dp += __shfl_xor_sync(0xffffffffu, dp, off);
    }
    if (lane == 0) { red[0][warp] = na; red[1][warp] = nb; red[2][warp] = dp; }
    __syncthreads();
    if (t == 0) {
        na = red[0][0] + red[0][1] + red[0][2] + red[0][3];
        nb = red[1][0] + red[1][1] + red[1][2] + red[1][3];
        dp = red[2][0] + red[2][1] + red[2][2] + red[2][3];
        out[b] = -dp * rsqrtf(fmaxf(na, 1e-12f)) * rsqrtf(fmaxf(nb, 1e-12f));
    }
}

// ---------------------------------------------------------------------------
extern "C" void kernel_launch(void* const* d_in, const int* in_sizes, int n_in,
                              void* d_out, int out_size) {
    const int*   field_id   = (const int*)  d_in[0];
    const float* cand_pos   = (const float*)d_in[1];
    const int*   nt         = (const int*)  d_in[2];
    const float* npos       = (const float*)d_in[3];
    const float* text_table = (const float*)d_in[4];
    const float* field_tab  = (const float*)d_in[5];
    const float* cand_W     = (const float*)d_in[6];
    const float* cand_b     = (const float*)d_in[7];
    const float* pos_W      = (const float*)d_in[8];
    const float* pos_b      = (const float*)d_in[9];
    const float* Wq         = (const float*)d_in[10];
    const float* bq         = (const float*)d_in[11];
    const float* Wk         = (const float*)d_in[12];
    const float* bk         = (const float*)d_in[13];
    const float* Wv         = (const float*)d_in[14];
    const float* bv         = (const float*)d_in[15];
    const float* Wo         = (const float*)d_in[16];
    const float* bo         = (const float*)d_in[17];
    const float* proj_W     = (const float*)d_in[18];
    const float* proj_b     = (const float*)d_in[19];
    float* out = (float*)d_out;

    float *Qb, *Ub, *r4b, *c0b, *xbarb, *wposb, *attb, *Ob, *encb;
    float *Mvp, *cvp, *Mcp, *ccp, *Rkp, *s1p, *Rqp, *sqp;
    cudaGetSymbolAddress((void**)&Qb,    g_Q);
    cudaGetSymbolAddress((void**)&Ub,    g_U);
    cudaGetSymbolAddress((void**)&r4b,   g_r4);
    cudaGetSymbolAddress((void**)&c0b,   g_c0);
    cudaGetSymbolAddress((void**)&xbarb, g_xbar);
    cudaGetSymbolAddress((void**)&wposb, g_wpos);
    cudaGetSymbolAddress((void**)&attb,  g_att);
    cudaGetSymbolAddress((void**)&Ob,    g_O);
    cudaGetSymbolAddress((void**)&encb,  g_enc);
    cudaGetSymbolAddress((void**)&Mvp,   g_Mv);
    cudaGetSymbolAddress((void**)&cvp,   g_cv);
    cudaGetSymbolAddress((void**)&Mcp,   g_Mc);
    cudaGetSymbolAddress((void**)&ccp,   g_cc);
    cudaGetSymbolAddress((void**)&Rkp,   g_Rk);
    cudaGetSymbolAddress((void**)&s1p,   g_s1);
    cudaGetSymbolAddress((void**)&Rqp,   g_Rq);
    cudaGetSymbolAddress((void**)&sqp,   g_sq);

    cudaFuncSetAttribute(attn_fused,
                         cudaFuncAttributeMaxDynamicSharedMemorySize, ATTN_SMEM);
    cudaFuncSetAttribute(wmma_gemm4<false, false, false>,
                         cudaFuncAttributeMaxDynamicSharedMemorySize, GSMEM_BYTES);
    cudaFuncSetAttribute(wmma_gemm4<true, false, false>,
                         cudaFuncAttributeMaxDynamicSharedMemorySize, GSMEM_BYTES);
    cudaFuncSetAttribute(wmma_gemm4<false, true, false>,
                         cudaFuncAttributeMaxDynamicSharedMemorySize, GSMEM_BYTES);
    cudaFuncSetAttribute(wmma_gemm4<false, false, true>,
                         cudaFuncAttributeMaxDynamicSharedMemorySize, GSMEM_BYTES);

    // ---- rank-4 folds: init + ONE merged split-K launch ----
    fold_init<<<(5 * DM + 255) / 256, 256>>>(Mvp, cvp, bv, Rkp, s1p, bk,
                                             Rqp, sqp, bq, Mcp, ccp, proj_b);
    fuse_all<<<dim3(DM / 128, FOLD_KSPLIT, 4), 128>>>(
        pos_W, pos_b, cand_W, cand_b,
        Wv + (size_t)Ee * DM, Wk + (size_t)Ee * DM, Wq + (size_t)Ee * DM, proj_W,
        Mvp, cvp, Rkp, s1p, Rqp, sqp, Mcp, ccp);

    // Q = gather(text_table) @ Wq_top  (1024 x 1024 x 512, gather fused)
    wmma_gemm4<false, false, true><<<dim3(8, 16, 1), 256, GSMEM_BYTES>>>(
        text_table, Ee, 0, Wq, DM, 0, Qb, DM, 0, nullptr, Ee, nt);
    q_post<<<(2 * Bsz * DM / 4 + 255) / 256, 256>>>(Qb, nullptr, npos, Rqp, sqp);

    // U_top = q_h @ Wk_top_h^T  (8 x [1024 x 512 x 128] NT)
    wmma_gemm4<true, false, false><<<dim3(4, 16, 8), 256, GSMEM_BYTES>>>(
        Qb, DM, 128, Wk, DM, 128, Ub, 8 * Ee, Ee, nullptr, DEPTH, nullptr);

    // per-(bq,h) score constants
    score_consts2<<<16 * Bsz / 8, 256>>>(Qb, Rkp, s1p, r4b, c0b);

    // fused gather-scores -> softmax -> xbar/wpos
    attn_fused<<<Bsz, 256, ATTN_SMEM>>>(nt, npos, Ub, r4b, c0b, text_table,
                                        xbarb, wposb);

    // att = xbar @ Wv_top  (8 x [1024 x 128 x 512])
    wmma_gemm4<false, false, false><<<dim3(1, 16, 8), 256, GSMEM_BYTES>>>(
        xbarb, 8 * Ee, Ee, Wv, DM, 128, attb, DM, 128, nullptr, Ee, nullptr);
    att_post<<<(2 * Bsz * DM / 4 + 255) / 256, 256>>>(attb, wposb, Mvp, cvp);

    // O = att @ Wo + bo  (1024 x 1024 x 1024)
    wmma_gemm4<false, false, false><<<dim3(8, 16, 1), 256, GSMEM_BYTES>>>(
        attb, DM, 0, Wo, DM, 0, Ob, DM, 0, bo, DM, nullptr);

    // enc = max-pool(O rows) @ proj_W[512:,:] + cc  (pool fused)
    wmma_gemm4<false, true, false><<<dim3(4, 8, 1), 256, GSMEM_BYTES>>>(
        Ob, DM, 0, proj_W + (size_t)Ee * Ee, Ee, 0, encb, Ee, 0, ccp, DM, nullptr);

    // cosine loss
    cosine_kernel<<<Bsz, 128>>>(encb, cand_pos, Mcp, field_id, field_tab, out);
}